// round 10
// baseline (speedup 1.0000x reference)
#include <cuda_runtime.h>
#include <cuda_bf16.h>
#include <math.h>
#include <cstdint>

// ---------------------------------------------------------------------------
// AdaLoRAWithBase restructured:
//   out = x + x@base + sum_r t[b,r] * x_b[b,:,r],  t[b,r] = sum_c x[b,c]*x_a[b,c,r]
//   [x_a|x_b] = GELU(LN(ada)@W1+b1) @ W2 + b2
// R10: gemm2 = R8 config (mma.sync pipe-saturated ~90us). Launch-count cuts:
//   reduce1 fused into k13 tail (last-z-CTA), t-reduction fused into gemm2
//   tail (last-x_a-CTA). Both deadlock-free (no CTA ever waits).
// ---------------------------------------------------------------------------

namespace {
constexpr int Bsz = 256;
constexpr int Dd  = 1024;
constexpr int Aa  = 1024;
constexpr int Rr  = 8;
constexpr int W2N = Dd * Rr * 2;     // 16384
constexpr int XBN = Dd * Rr;         // 8192 (x_b width)
constexpr int Kd  = 1024;

constexpr int BM = 128, BK = 32;
constexpr int A_ROWB = 80;           // bytes per A smem row (40 bf16)
}

// Scratch (device globals)
__device__ __align__(16) float g_w[(size_t)Bsz * XBN];    // 8 MB (x_b only)
__device__ __align__(16) float g_tp[64 * Bsz * Rr];       // per-CTA t partials
__device__ __align__(16) float g_t[Bsz * Rr];             // reduced t
__device__ __align__(16) float g_p1[4 * Bsz * Dd];
__device__ __align__(16) float g_p3[4 * Bsz * Dd];
__device__ __align__(16) __nv_bfloat16 g_Chi[Bsz * Kd];
__device__ __align__(16) __nv_bfloat16 g_Clo[Bsz * Kd];
__device__ __align__(16) __nv_bfloat16 g_Ahi[Bsz * Kd];
__device__ __align__(16) __nv_bfloat16 g_Alo[Bsz * Kd];
__device__ __align__(16) __nv_bfloat16 g_Xhi[Bsz * Kd];
__device__ __align__(16) __nv_bfloat16 g_Xlo[Bsz * Kd];
__device__ int g_ctr1[32];   // k13 gemm1 tile counters (16 bx x 2 by)
__device__ int g_ctr2;       // gemm2 x_a CTA counter

// ---------------------------------------------------------------------------
// PTX helpers (baseline sm_80+)
// ---------------------------------------------------------------------------
__device__ __forceinline__ uint32_t smem_u32(const void* p) {
    uint32_t a;
    asm("{ .reg .u64 t; cvta.to.shared.u64 t, %1; cvt.u32.u64 %0, t; }" : "=r"(a) : "l"(p));
    return a;
}
__device__ __forceinline__ void cp_async16(uint32_t saddr, const void* gaddr) {
    asm volatile("cp.async.cg.shared.global [%0], [%1], 16;" :: "r"(saddr), "l"(gaddr) : "memory");
}
__device__ __forceinline__ void cp_commit() {
    asm volatile("cp.async.commit_group;" ::: "memory");
}
template <int N>
__device__ __forceinline__ void cp_wait() {
    asm volatile("cp.async.wait_group %0;" :: "n"(N) : "memory");
}
__device__ __forceinline__ void ldsm_x4(uint32_t& r0, uint32_t& r1, uint32_t& r2, uint32_t& r3,
                                        uint32_t addr) {
    asm volatile("ldmatrix.sync.aligned.m8n8.x4.shared.b16 {%0,%1,%2,%3}, [%4];"
                 : "=r"(r0), "=r"(r1), "=r"(r2), "=r"(r3) : "r"(addr));
}
__device__ __forceinline__ void ldsm_x4_trans(uint32_t& r0, uint32_t& r1, uint32_t& r2,
                                              uint32_t& r3, uint32_t addr) {
    asm volatile("ldmatrix.sync.aligned.m8n8.x4.trans.shared.b16 {%0,%1,%2,%3}, [%4];"
                 : "=r"(r0), "=r"(r1), "=r"(r2), "=r"(r3) : "r"(addr));
}
__device__ __forceinline__ void mma16816(float* c, uint32_t a0, uint32_t a1, uint32_t a2,
                                         uint32_t a3, uint32_t b0, uint32_t b1) {
    asm volatile(
        "mma.sync.aligned.m16n8k16.row.col.f32.bf16.bf16.f32 "
        "{%0,%1,%2,%3},{%4,%5,%6,%7},{%8,%9},{%0,%1,%2,%3};"
        : "+f"(c[0]), "+f"(c[1]), "+f"(c[2]), "+f"(c[3])
        : "r"(a0), "r"(a1), "r"(a2), "r"(a3), "r"(b0), "r"(b1));
}

// ---------------------------------------------------------------------------
// Merged pre-pass: blocks [0,256) LayerNorm; blocks [256,768) split x.
// Block 0 also zeroes the tail counters (stream-serial => visible to k13/gemm2).
// ---------------------------------------------------------------------------
__global__ void __launch_bounds__(256) prepass_kernel(
    const float* __restrict__ ada, const float* __restrict__ gamma,
    const float* __restrict__ beta, const float* __restrict__ x)
{
    if (blockIdx.x == 0) {
        if (threadIdx.x < 32) g_ctr1[threadIdx.x] = 0;
        if (threadIdx.x == 32) g_ctr2 = 0;
    }
    if (blockIdx.x < 256) {
        int b = blockIdx.x;
        const float* row = ada + (size_t)b * Aa;
        float s = 0.f, s2 = 0.f;
        for (int i = threadIdx.x; i < Aa; i += blockDim.x) {
            float v = row[i]; s += v; s2 += v * v;
        }
        #pragma unroll
        for (int o = 16; o; o >>= 1) {
            s  += __shfl_down_sync(0xFFFFFFFFu, s,  o);
            s2 += __shfl_down_sync(0xFFFFFFFFu, s2, o);
        }
        __shared__ float red0[8], red1[8], mv[2];
        int wid = threadIdx.x >> 5, lid = threadIdx.x & 31;
        if (lid == 0) { red0[wid] = s; red1[wid] = s2; }
        __syncthreads();
        if (threadIdx.x == 0) {
            float ts = 0.f, ts2 = 0.f;
            #pragma unroll
            for (int i = 0; i < 8; i++) { ts += red0[i]; ts2 += red1[i]; }
            float mu = ts * (1.f / Aa);
            float var = ts2 * (1.f / Aa) - mu * mu;
            mv[0] = mu; mv[1] = rsqrtf(var + 1e-5f);
        }
        __syncthreads();
        float mu = mv[0], rs = mv[1];
        for (int i = threadIdx.x; i < Aa; i += blockDim.x) {
            float v = (row[i] - mu) * rs * gamma[i] + beta[i];
            __nv_bfloat16 hi = __float2bfloat16(v);
            g_Chi[(size_t)b * Aa + i] = hi;
            g_Clo[(size_t)b * Aa + i] = __float2bfloat16(v - __bfloat162float(hi));
        }
    } else {
        int i = ((blockIdx.x - 256) * 256 + threadIdx.x) * 2;
        float v0 = x[i], v1 = x[i + 1];
        __nv_bfloat16 h0 = __float2bfloat16(v0), h1 = __float2bfloat16(v1);
        float l0 = v0 - __bfloat162float(h0), l1 = v1 - __bfloat162float(h1);
        *reinterpret_cast<__nv_bfloat162*>(&g_Xhi[i]) = __halves2bfloat162(h0, h1);
        *reinterpret_cast<__nv_bfloat162*>(&g_Xlo[i]) =
            __halves2bfloat162(__float2bfloat16(l0), __float2bfloat16(l1));
    }
}

// ---------------------------------------------------------------------------
// Load helpers (R8 layout). Stage: A-hi [0,10240), A-lo [10240,20480),
// raw fp32 B [20480, 20480+128*BN_). Raw chunks are thread-self-owned.
// ---------------------------------------------------------------------------
template <int N_, int NTHR>
__device__ __forceinline__ void load_A(
    uint32_t sstage, const __nv_bfloat16* __restrict__ ahi,
    const __nv_bfloat16* __restrict__ alo, int m0, int k0, int tid)
{
    #pragma unroll
    for (int it = 0; it < 1024 / NTHR; it++) {
        int idx = tid + it * NTHR;
        if (idx < 512) {
            int row = idx >> 2, ch = idx & 3;
            cp_async16(sstage + row * A_ROWB + ch * 16,
                       &ahi[(size_t)(m0 + row) * Kd + k0 + ch * 8]);
        } else {
            int l = idx - 512, row = l >> 2, ch = l & 3;
            cp_async16(sstage + 10240 + row * A_ROWB + ch * 16,
                       &alo[(size_t)(m0 + row) * Kd + k0 + ch * 8]);
        }
    }
    cp_commit();
}

template <int BN_, int N_, int NTHR>
__device__ __forceinline__ void load_raw(
    uint32_t sstage, const float* __restrict__ Braw, int n0, int k0, int tid)
{
    constexpr int RCHR = BN_ / 4;
    constexpr int RC = 8 * BN_;
    #pragma unroll
    for (int it = 0; it < RC / NTHR; it++) {
        int c = tid + it * NTHR;
        int row = c / RCHR, ch = c % RCHR;
        cp_async16(sstage + 20480 + c * 16,
                   &Braw[(size_t)(k0 + row) * N_ + n0 + ch * 4]);
    }
    cp_commit();
}

template <int BN_, int NTHR>
__device__ __forceinline__ void conv_b(char* smem, uint32_t raw_off, uint32_t bb_off,
                                       uint32_t bb_half, int tid)
{
    constexpr int B_RL = BN_ + 8;
    constexpr int RC = 8 * BN_;
    #pragma unroll
    for (int i = 0; i < RC / NTHR; i++) {
        int c = tid + i * NTHR;
        float4 v = *reinterpret_cast<const float4*>(smem + raw_off + c * 16);
        int row = c / (BN_ / 4);
        int col = (c % (BN_ / 4)) * 4;
        __nv_bfloat16 h0 = __float2bfloat16(v.x), h1 = __float2bfloat16(v.y);
        __nv_bfloat16 h2 = __float2bfloat16(v.z), h3 = __float2bfloat16(v.w);
        float l0 = v.x - __bfloat162float(h0), l1 = v.y - __bfloat162float(h1);
        float l2 = v.z - __bfloat162float(h2), l3 = v.w - __bfloat162float(h3);
        uint32_t eoff = (uint32_t)(row * B_RL + col) * 2;
        char* hi = smem + bb_off + eoff;
        char* lo = smem + bb_off + bb_half + eoff;
        *reinterpret_cast<__nv_bfloat162*>(hi)     = __halves2bfloat162(h0, h1);
        *reinterpret_cast<__nv_bfloat162*>(hi + 4) = __halves2bfloat162(h2, h3);
        *reinterpret_cast<__nv_bfloat162*>(lo)     =
            __halves2bfloat162(__float2bfloat16(l0), __float2bfloat16(l1));
        *reinterpret_cast<__nv_bfloat162*>(lo + 4) =
            __halves2bfloat162(__float2bfloat16(l2), __float2bfloat16(l3));
    }
}

// ---------------------------------------------------------------------------
// Unified bf16 hi/lo 3-pass MMA GEMM (R8 pipeline: PSTG=2 split-commit,
// double-buffered bb, 2 CTAs/SM). 8 warps (2m x 4n).
// FUSE_T: x_a-half CTAs produce t partials; last x_a CTA reduces g_tp -> g_t.
// FUSE_R1: gemm1-side CTAs (z<SK): last-of-4 z-CTAs reduces partials+GELU+split.
// ---------------------------------------------------------------------------
template <int BN_, int SK, bool HAS_BIAS, int N_, bool DUAL, bool FUSE_T, bool FUSE_R1>
__global__ void __launch_bounds__(256, 2) gemm_mma_kernel(
    const __nv_bfloat16* __restrict__ ahi0, const __nv_bfloat16* __restrict__ alo0,
    const float* __restrict__ Braw0, float* __restrict__ C0,
    const __nv_bfloat16* __restrict__ ahi1, const __nv_bfloat16* __restrict__ alo1,
    const float* __restrict__ Braw1, float* __restrict__ C1,
    const float* __restrict__ bias, const float* __restrict__ xsrc)
{
    constexpr int NTHR = 256;
    constexpr int NWN  = 4;
    constexpr int WN   = BN_ / NWN;
    constexpr int NT   = WN / 8;
    constexpr int B_RL = BN_ + 8;
    constexpr int STG  = 20480 + 128 * BN_;
    constexpr int OFF_BB = 2 * STG;
    constexpr int BB_HALF = 32 * B_RL * 2;
    constexpr int BB_SZ = 2 * BB_HALF;
    constexpr int KITERS = Kd / SK / BK;

    extern __shared__ char smem[];
    uint32_t sb = smem_u32(smem);
    const int tid = threadIdx.x, lane = tid & 31, wid = tid >> 5;
    const int warp_m = wid >> 2, warp_n = wid & 3;
    const int m0 = blockIdx.y * BM, n0 = blockIdx.x * BN_;

    const bool is_p0 = (blockIdx.z < SK);
    int z = blockIdx.z;
    const __nv_bfloat16* ahi = ahi0;
    const __nv_bfloat16* alo = alo0;
    const float* Braw = Braw0;
    float* C = C0;
    if (DUAL && !is_p0) {
        z -= SK; ahi = ahi1; alo = alo1; Braw = Braw1; C = C1;
    }
    const int kb = z * (Kd / SK);

    float acc[4][NT][4];
    #pragma unroll
    for (int i = 0; i < 4; i++)
        #pragma unroll
        for (int j = 0; j < NT; j++)
            #pragma unroll
            for (int r = 0; r < 4; r++) acc[i][j][r] = 0.f;

    float2 biasv[NT];
    if constexpr (HAS_BIAS) {
        #pragma unroll
        for (int nt = 0; nt < NT; nt++)
            biasv[nt] = *reinterpret_cast<const float2*>(
                &bias[n0 + warp_n * WN + nt * 8 + (lane & 3) * 2]);
    }

    // prologue
    load_raw<BN_, N_, NTHR>(sb, Braw, n0, kb, tid);
    load_A<N_, NTHR>(sb, ahi, alo, m0, kb, tid);
    cp_commit();
    load_raw<BN_, N_, NTHR>(sb + STG, Braw, n0, kb + BK, tid);
    load_A<N_, NTHR>(sb + STG, ahi, alo, m0, kb + BK, tid);
    cp_wait<0>();
    conv_b<BN_, NTHR>(smem, 20480, OFF_BB, BB_HALF, tid);
    __syncthreads();

    const int a_row_in_tile = lane & 15;
    const int a_colblk = (lane >> 4) << 3;
    const int b_krow = (lane & 7) + ((lane >> 3) & 1) * 8;
    const int b_cofs = warp_n * WN + ((lane >> 4) & 1) * 8;

    for (int kt = 0; kt < KITERS; kt++) {
        cp_wait<1>();
        __syncthreads();

        uint32_t abase = sb + (kt & 1) * STG;
        uint32_t bbase = sb + OFF_BB + (kt & 1) * BB_SZ;

        if (kt + 2 < KITERS)
            load_raw<BN_, N_, NTHR>(abase, Braw, n0, kb + (kt + 2) * BK, tid);
        if (kt + 1 < KITERS)
            conv_b<BN_, NTHR>(smem, ((kt + 1) & 1) * STG + 20480,
                              OFF_BB + ((kt + 1) & 1) * BB_SZ, BB_HALF, tid);

        #pragma unroll
        for (int ks = 0; ks < 2; ks++) {
            uint32_t af[4][4], bf[NT][2], bl2[NT][2];
            #pragma unroll
            for (int mt = 0; mt < 4; mt++) {
                int row = warp_m * 64 + mt * 16 + a_row_in_tile;
                uint32_t off = (uint32_t)(row * 40 + ks * 16 + a_colblk) * 2;
                ldsm_x4(af[mt][0], af[mt][1], af[mt][2], af[mt][3], abase + off);
            }
            #pragma unroll
            for (int ntp = 0; ntp < NT / 2; ntp++) {
                uint32_t off = (uint32_t)((ks * 16 + b_krow) * B_RL + b_cofs + ntp * 16) * 2;
                ldsm_x4_trans(bf[2*ntp][0], bf[2*ntp][1], bf[2*ntp+1][0], bf[2*ntp+1][1],
                              bbase + off);
            }
            #pragma unroll
            for (int mt = 0; mt < 4; mt++)
                #pragma unroll
                for (int nt = 0; nt < NT; nt++)
                    mma16816(acc[mt][nt], af[mt][0], af[mt][1], af[mt][2], af[mt][3],
                             bf[nt][0], bf[nt][1]);
            #pragma unroll
            for (int ntp = 0; ntp < NT / 2; ntp++) {
                uint32_t off = (uint32_t)((ks * 16 + b_krow) * B_RL + b_cofs + ntp * 16) * 2;
                ldsm_x4_trans(bl2[2*ntp][0], bl2[2*ntp][1], bl2[2*ntp+1][0], bl2[2*ntp+1][1],
                              bbase + BB_HALF + off);
            }
            #pragma unroll
            for (int mt = 0; mt < 4; mt++)
                #pragma unroll
                for (int nt = 0; nt < NT; nt++)
                    mma16816(acc[mt][nt], af[mt][0], af[mt][1], af[mt][2], af[mt][3],
                             bl2[nt][0], bl2[nt][1]);
            #pragma unroll
            for (int mt = 0; mt < 4; mt++) {
                int row = warp_m * 64 + mt * 16 + a_row_in_tile;
                uint32_t off = (uint32_t)(row * 40 + ks * 16 + a_colblk) * 2;
                ldsm_x4(af[mt][0], af[mt][1], af[mt][2], af[mt][3], abase + 10240 + off);
            }
            #pragma unroll
            for (int mt = 0; mt < 4; mt++)
                #pragma unroll
                for (int nt = 0; nt < NT; nt++)
                    mma16816(acc[mt][nt], af[mt][0], af[mt][1], af[mt][2], af[mt][3],
                             bf[nt][0], bf[nt][1]);
        }

        __syncthreads();
        if (kt + 2 < KITERS)
            load_A<N_, NTHR>(abase, ahi, alo, m0, kb + (kt + 2) * BK, tid);
    }

    if (FUSE_T && blockIdx.x < (XBN / BN_)) {
        // x_a half: t partials. Each nt fragment = one d (8 r-columns).
        float* tpart = (float*)smem;                     // [4][128][8]
        float* x_s = (float*)(smem + 4 * 128 * 8 * 4);   // [128][16]
        __syncthreads();
        {
            int d0 = n0 / 8;                             // 16 d per CTA
            int row = tid >> 1, c4 = (tid & 1) * 2;
            float4 v = *reinterpret_cast<const float4*>(
                &xsrc[(size_t)(m0 + row) * Dd + d0 + c4 * 4]);
            float4 v2 = *reinterpret_cast<const float4*>(
                &xsrc[(size_t)(m0 + row) * Dd + d0 + c4 * 4 + 4]);
            *reinterpret_cast<float4*>(&x_s[row * 16 + c4 * 4]) = v;
            *reinterpret_cast<float4*>(&x_s[row * 16 + c4 * 4 + 4]) = v2;
        }
        __syncthreads();

        int r0 = (lane & 3) * 2;
        #pragma unroll
        for (int mt = 0; mt < 4; mt++) {
            int row_a = warp_m * 64 + mt * 16 + (lane >> 2);
            int row_b = row_a + 8;
            float t00 = 0.f, t01 = 0.f, t10 = 0.f, t11 = 0.f;
            #pragma unroll
            for (int nt = 0; nt < NT; nt++) {
                int dl = warp_n * NT + nt;
                float xa = x_s[row_a * 16 + dl];
                float xb = x_s[row_b * 16 + dl];
                float bx = 0.f, by = 0.f;
                if constexpr (HAS_BIAS) { bx = biasv[nt].x; by = biasv[nt].y; }
                t00 += xa * (acc[mt][nt][0] + bx);
                t01 += xa * (acc[mt][nt][1] + by);
                t10 += xb * (acc[mt][nt][2] + bx);
                t11 += xb * (acc[mt][nt][3] + by);
            }
            tpart[(warp_n * 128 + row_a) * 8 + r0]     = t00;
            tpart[(warp_n * 128 + row_a) * 8 + r0 + 1] = t01;
            tpart[(warp_n * 128 + row_b) * 8 + r0]     = t10;
            tpart[(warp_n * 128 + row_b) * 8 + r0 + 1] = t11;
        }
        __syncthreads();
        #pragma unroll
        for (int i = 0; i < 4; i++) {
            int pr = tid + i * NTHR;
            int row = pr >> 3, r = pr & 7;
            float s = 0.f;
            #pragma unroll
            for (int w = 0; w < 4; w++)
                s += tpart[(w * 128 + row) * 8 + r];
            g_tp[((size_t)blockIdx.x * Bsz + m0 + row) * Rr + r] = s;
        }

        // ---- last x_a CTA reduces g_tp -> g_t (deadlock-free tail) ----
        __threadfence();
        __shared__ int lastf;
        if (tid == 0)
            lastf = (atomicAdd(&g_ctr2, 1) == 2 * (XBN / BN_) - 1);
        __syncthreads();
        if (lastf) {
            for (int i = tid; i < Bsz * Rr; i += NTHR) {
                float s = 0.f;
                #pragma unroll 4
                for (int w = 0; w < XBN / BN_; w++)
                    s += g_tp[(size_t)w * Bsz * Rr + i];
                g_t[i] = s;
            }
        }
        return;
    }

    // normal / x_b store
    float* Cw;
    if constexpr (SK == 1) {
        Cw = C;
    } else {
        Cw = C + (size_t)z * Bsz * N_;
    }
    int nbase = n0;
    int nstride = N_;
    if constexpr (FUSE_T) { nbase = n0 - XBN; nstride = XBN; }
    #pragma unroll
    for (int mt = 0; mt < 4; mt++) {
        int row0 = m0 + warp_m * 64 + mt * 16 + (lane >> 2);
        #pragma unroll
        for (int nt = 0; nt < NT; nt++) {
            int col = nbase + warp_n * WN + nt * 8 + (lane & 3) * 2;
            float bx = 0.f, by = 0.f;
            if constexpr (HAS_BIAS) { bx = biasv[nt].x; by = biasv[nt].y; }
            float2 v0 = make_float2(acc[mt][nt][0] + bx, acc[mt][nt][1] + by);
            float2 v1 = make_float2(acc[mt][nt][2] + bx, acc[mt][nt][3] + by);
            *reinterpret_cast<float2*>(&Cw[(size_t)row0 * nstride + col]) = v0;
            *reinterpret_cast<float2*>(&Cw[(size_t)(row0 + 8) * nstride + col]) = v1;
        }
    }

    // ---- FUSE_R1: last z-CTA of each gemm1 tile reduces + GELU + split ----
    if (FUSE_R1 && is_p0) {
        __threadfence();
        __shared__ int lastr;
        if (tid == 0)
            lastr = (atomicAdd(&g_ctr1[blockIdx.y * 16 + blockIdx.x], 1) == SK - 1);
        __syncthreads();
        if (lastr) {
            // reduce tile (m0..m0+127, n0..n0+BN_-1) of gemm1 partials in C0
            for (int i = tid; i < (128 * BN_) / 4; i += NTHR) {
                int row = i / (BN_ / 4), c4 = (i % (BN_ / 4)) * 4;
                size_t e = (size_t)(m0 + row) * N_ + n0 + c4;
                float4 s = *reinterpret_cast<const float4*>(&C0[e]);
                #pragma unroll
                for (int zz = 1; zz < SK; zz++) {
                    float4 p = *reinterpret_cast<const float4*>(
                        &C0[(size_t)zz * Bsz * N_ + e]);
                    s.x += p.x; s.y += p.y; s.z += p.z; s.w += p.w;
                }
                float4 bb = *reinterpret_cast<const float4*>(&bias[n0 + c4]);
                float u[4] = {s.x + bb.x, s.y + bb.y, s.z + bb.z, s.w + bb.w};
                __nv_bfloat16 hi[4], lo[4];
                #pragma unroll
                for (int q = 0; q < 4; q++) {
                    float g = 0.5f * u[q] * (1.f + erff(u[q] * 0.70710678118654752f));
                    hi[q] = __float2bfloat16(g);
                    lo[q] = __float2bfloat16(g - __bfloat162float(hi[q]));
                }
                *reinterpret_cast<__nv_bfloat162*>(&g_Ahi[e])     = __halves2bfloat162(hi[0], hi[1]);
                *reinterpret_cast<__nv_bfloat162*>(&g_Ahi[e + 2]) = __halves2bfloat162(hi[2], hi[3]);
                *reinterpret_cast<__nv_bfloat162*>(&g_Alo[e])     = __halves2bfloat162(lo[0], lo[1]);
                *reinterpret_cast<__nv_bfloat162*>(&g_Alo[e + 2]) = __halves2bfloat162(lo[2], lo[3]);
            }
        }
    }
}

// ---------------------------------------------------------------------------
// reduce3: out = x + sum_z p3[z] + rank-8 epilogue (t from g_t).
// ---------------------------------------------------------------------------
__global__ void __launch_bounds__(256) reduce3_kernel(
    const float* __restrict__ x, float* __restrict__ out)
{
    int b = blockIdx.y;
    __shared__ float t_s[Rr];
    if (threadIdx.x < Rr) t_s[threadIdx.x] = g_t[b * Rr + threadIdx.x];
    __syncthreads();

    int o = blockIdx.x * 512 + threadIdx.x * 2;
    size_t e = (size_t)b * Dd + o;
    float2 s = *reinterpret_cast<const float2*>(&x[e]);
    #pragma unroll
    for (int z = 0; z < 4; z++) {
        float2 p = *reinterpret_cast<const float2*>(&g_p3[z * (Bsz * Dd) + e]);
        s.x += p.x; s.y += p.y;
    }
    float t0 = t_s[0], t1 = t_s[1], t2 = t_s[2], t3 = t_s[3];
    float t4 = t_s[4], t5 = t_s[5], t6 = t_s[6], t7 = t_s[7];
    const float* wb = &g_w[(size_t)b * XBN + (size_t)o * Rr];
    float4 w0 = *reinterpret_cast<const float4*>(wb);
    float4 w1 = *reinterpret_cast<const float4*>(wb + 4);
    float4 w2 = *reinterpret_cast<const float4*>(wb + 8);
    float4 w3 = *reinterpret_cast<const float4*>(wb + 12);
    float lr0 = t0*w0.x + t1*w0.y + t2*w0.z + t3*w0.w
              + t4*w1.x + t5*w1.y + t6*w1.z + t7*w1.w;
    float lr1 = t0*w2.x + t1*w2.y + t2*w2.z + t3*w2.w
              + t4*w3.x + t5*w3.y + t6*w3.z + t7*w3.w;
    *reinterpret_cast<float2*>(&out[e]) = make_float2(s.x + lr0, s.y + lr1);
}

// ---------------------------------------------------------------------------
extern "C" void kernel_launch(void* const* d_in, const int* in_sizes, int n_in,
                              void* d_out, int out_size)
{
    const float* x    = (const float*)d_in[0];
    const float* ada  = (const float*)d_in[1];
    const float* base = (const float*)d_in[2];
    const float* gam  = (const float*)d_in[3];
    const float* bet  = (const float*)d_in[4];
    const float* W1   = (const float*)d_in[5];
    const float* b1   = (const float*)d_in[6];
    const float* W2   = (const float*)d_in[7];
    const float* b2   = (const float*)d_in[8];
    float* out = (float*)d_out;

    constexpr int SMEM64  = 2 * (20480 + 128 * 64)  + 2 * (2 * 32 * 72 * 2);   // 75776
    constexpr int SMEM128 = 2 * (20480 + 128 * 128) + 2 * (2 * 32 * 136 * 2);  // 108544

    float *w_p, *p1_p, *p3_p;
    __nv_bfloat16 *chi_p, *clo_p, *ahi_p, *alo_p, *xhi_p, *xlo_p;
    cudaGetSymbolAddress((void**)&w_p,  g_w);
    cudaGetSymbolAddress((void**)&p1_p, g_p1);
    cudaGetSymbolAddress((void**)&p3_p, g_p3);
    cudaGetSymbolAddress((void**)&chi_p, g_Chi);
    cudaGetSymbolAddress((void**)&clo_p, g_Clo);
    cudaGetSymbolAddress((void**)&ahi_p, g_Ahi);
    cudaGetSymbolAddress((void**)&alo_p, g_Alo);
    cudaGetSymbolAddress((void**)&xhi_p, g_Xhi);
    cudaGetSymbolAddress((void**)&xlo_p, g_Xlo);

    // k13: BN=64, SK=4, DUAL, fused reduce1 tail (bias = b1 for the tail)
    auto k13 = gemm_mma_kernel<64, 4, false, 1024, true, false, true>;
    // gemm2: BN=128, SK=1, bias, fused t epilogue + last-CTA t reduce
    auto k2  = gemm_mma_kernel<128, 1, true, 16384, false, true, false>;

    cudaFuncSetAttribute((const void*)k13,
                         cudaFuncAttributeMaxDynamicSharedMemorySize, SMEM64);
    cudaFuncSetAttribute((const void*)k2,
                         cudaFuncAttributeMaxDynamicSharedMemorySize, SMEM128);

    // prepass: counters + LN (256 blocks) + x split (512 blocks)
    prepass_kernel<<<768, 256>>>(ada, gam, bet, x);

    // GEMM1 + GEMM3 fused launch; last gemm1 z-CTA per tile does reduce1
    k13<<<dim3(16, 2, 8), 256, SMEM64>>>(
        chi_p, clo_p, W1, p1_p,
        xhi_p, xlo_p, base, p3_p, b1, nullptr);

    // GEMM2: x_a half -> t partials (+ last-CTA reduce to g_t), x_b half -> g_w
    k2<<<dim3(W2N / 128, Bsz / BM, 1), 256, SMEM128>>>(
        ahi_p, alo_p, W2, w_p,
        nullptr, nullptr, nullptr, nullptr, b2, x);

    // final epilogue
    reduce3_kernel<<<dim3(2, Bsz), 256>>>(x, out);
}

// round 12
// speedup vs baseline: 1.2792x; 1.2792x over previous
#include <cuda_runtime.h>
#include <cuda_bf16.h>
#include <math.h>
#include <cstdint>

// ---------------------------------------------------------------------------
// AdaLoRAWithBase restructured:
//   out = x + x@base + sum_r t[b,r] * x_b[b,:,r],  t[b,r] = sum_c x[b,c]*x_a[b,c,r]
//   [x_a|x_b] = GELU(LN(ada)@W1+b1) @ W2 + b2
// R12: R7 gemm core (gemm2 at mma.sync HW rate) + MLP-optimized reduce1/reduce3.
// Fixes R11's broken x-tile load in the FUSE_T tail (512-thread indexing).
// ---------------------------------------------------------------------------

namespace {
constexpr int Bsz = 256;
constexpr int Dd  = 1024;
constexpr int Aa  = 1024;
constexpr int Rr  = 8;
constexpr int W2N = Dd * Rr * 2;     // 16384
constexpr int XBN = Dd * Rr;         // 8192 (x_b width)
constexpr int Kd  = 1024;

constexpr int BM = 128, BK = 32;
constexpr int PSTG = 3;
constexpr int A_ROWB = 80;           // bytes per A smem row (40 bf16)
}

// Scratch (device globals)
__device__ __align__(16) float g_w[(size_t)Bsz * XBN];   // 8 MB (x_b only)
__device__ __align__(16) float g_tp[32 * Bsz * Rr];      // per-CTA t partials
__device__ __align__(16) float g_p1[4 * Bsz * Dd];
__device__ __align__(16) float g_p3[4 * Bsz * Dd];
__device__ __align__(16) __nv_bfloat16 g_Chi[Bsz * Kd];
__device__ __align__(16) __nv_bfloat16 g_Clo[Bsz * Kd];
__device__ __align__(16) __nv_bfloat16 g_Ahi[Bsz * Kd];
__device__ __align__(16) __nv_bfloat16 g_Alo[Bsz * Kd];
__device__ __align__(16) __nv_bfloat16 g_Xhi[Bsz * Kd];
__device__ __align__(16) __nv_bfloat16 g_Xlo[Bsz * Kd];

// ---------------------------------------------------------------------------
// PTX helpers (baseline sm_80+)
// ---------------------------------------------------------------------------
__device__ __forceinline__ uint32_t smem_u32(const void* p) {
    uint32_t a;
    asm("{ .reg .u64 t; cvta.to.shared.u64 t, %1; cvt.u32.u64 %0, t; }" : "=r"(a) : "l"(p));
    return a;
}
__device__ __forceinline__ void cp_async16(uint32_t saddr, const void* gaddr) {
    asm volatile("cp.async.cg.shared.global [%0], [%1], 16;" :: "r"(saddr), "l"(gaddr) : "memory");
}
__device__ __forceinline__ void cp_commit() {
    asm volatile("cp.async.commit_group;" ::: "memory");
}
template <int N>
__device__ __forceinline__ void cp_wait() {
    asm volatile("cp.async.wait_group %0;" :: "n"(N) : "memory");
}
__device__ __forceinline__ void ldsm_x4(uint32_t& r0, uint32_t& r1, uint32_t& r2, uint32_t& r3,
                                        uint32_t addr) {
    asm volatile("ldmatrix.sync.aligned.m8n8.x4.shared.b16 {%0,%1,%2,%3}, [%4];"
                 : "=r"(r0), "=r"(r1), "=r"(r2), "=r"(r3) : "r"(addr));
}
__device__ __forceinline__ void ldsm_x2_trans(uint32_t& r0, uint32_t& r1, uint32_t addr) {
    asm volatile("ldmatrix.sync.aligned.m8n8.x2.trans.shared.b16 {%0,%1}, [%2];"
                 : "=r"(r0), "=r"(r1) : "r"(addr));
}
__device__ __forceinline__ void mma16816(float* c, uint32_t a0, uint32_t a1, uint32_t a2,
                                         uint32_t a3, uint32_t b0, uint32_t b1) {
    asm volatile(
        "mma.sync.aligned.m16n8k16.row.col.f32.bf16.bf16.f32 "
        "{%0,%1,%2,%3},{%4,%5,%6,%7},{%8,%9},{%0,%1,%2,%3};"
        : "+f"(c[0]), "+f"(c[1]), "+f"(c[2]), "+f"(c[3])
        : "r"(a0), "r"(a1), "r"(a2), "r"(a3), "r"(b0), "r"(b1));
}

// ---------------------------------------------------------------------------
// Merged pre-pass: blocks [0,256) do LayerNorm rows; blocks [256,768) split x.
// ---------------------------------------------------------------------------
__global__ void __launch_bounds__(256) prepass_kernel(
    const float* __restrict__ ada, const float* __restrict__ gamma,
    const float* __restrict__ beta, const float* __restrict__ x)
{
    if (blockIdx.x < 256) {
        int b = blockIdx.x;
        const float* row = ada + (size_t)b * Aa;
        float s = 0.f, s2 = 0.f;
        for (int i = threadIdx.x; i < Aa; i += blockDim.x) {
            float v = row[i]; s += v; s2 += v * v;
        }
        #pragma unroll
        for (int o = 16; o; o >>= 1) {
            s  += __shfl_down_sync(0xFFFFFFFFu, s,  o);
            s2 += __shfl_down_sync(0xFFFFFFFFu, s2, o);
        }
        __shared__ float red0[8], red1[8], mv[2];
        int wid = threadIdx.x >> 5, lid = threadIdx.x & 31;
        if (lid == 0) { red0[wid] = s; red1[wid] = s2; }
        __syncthreads();
        if (threadIdx.x == 0) {
            float ts = 0.f, ts2 = 0.f;
            #pragma unroll
            for (int i = 0; i < 8; i++) { ts += red0[i]; ts2 += red1[i]; }
            float mu = ts * (1.f / Aa);
            float var = ts2 * (1.f / Aa) - mu * mu;
            mv[0] = mu; mv[1] = rsqrtf(var + 1e-5f);
        }
        __syncthreads();
        float mu = mv[0], rs = mv[1];
        for (int i = threadIdx.x; i < Aa; i += blockDim.x) {
            float v = (row[i] - mu) * rs * gamma[i] + beta[i];
            __nv_bfloat16 hi = __float2bfloat16(v);
            g_Chi[(size_t)b * Aa + i] = hi;
            g_Clo[(size_t)b * Aa + i] = __float2bfloat16(v - __bfloat162float(hi));
        }
    } else {
        int i = ((blockIdx.x - 256) * 256 + threadIdx.x) * 2;
        float v0 = x[i], v1 = x[i + 1];
        __nv_bfloat16 h0 = __float2bfloat16(v0), h1 = __float2bfloat16(v1);
        float l0 = v0 - __bfloat162float(h0), l1 = v1 - __bfloat162float(h1);
        *reinterpret_cast<__nv_bfloat162*>(&g_Xhi[i]) = __halves2bfloat162(h0, h1);
        *reinterpret_cast<__nv_bfloat162*>(&g_Xlo[i]) =
            __halves2bfloat162(__float2bfloat16(l0), __float2bfloat16(l1));
    }
}

// ---------------------------------------------------------------------------
// Unified bf16 hi/lo 3-pass MMA GEMM, fused fp32 B conversion, PSTG=3.
// FUSE_T: x_a-half CTAs (blockIdx.x < XBN/BN_) compute t partials.
// ---------------------------------------------------------------------------
template <int BN_, int N_, int NTHR>
__device__ __forceinline__ void load_grp(
    uint32_t sstage, const __nv_bfloat16* __restrict__ ahi,
    const __nv_bfloat16* __restrict__ alo, const float* __restrict__ Braw,
    int m0, int n0, int k0, int tid)
{
    constexpr int RCHR = BN_ / 4;
    constexpr int TOT = 1024 + 8 * BN_;
    #pragma unroll
    for (int it = 0; it < TOT / NTHR; it++) {
        int idx = tid + it * NTHR;
        if (idx < 512) {
            int row = idx >> 2, ch = idx & 3;
            cp_async16(sstage + row * A_ROWB + ch * 16,
                       &ahi[(size_t)(m0 + row) * Kd + k0 + ch * 8]);
        } else if (idx < 1024) {
            int l = idx - 512, row = l >> 2, ch = l & 3;
            cp_async16(sstage + 10240 + row * A_ROWB + ch * 16,
                       &alo[(size_t)(m0 + row) * Kd + k0 + ch * 8]);
        } else {
            int l = idx - 1024;
            int row = l / RCHR, ch = l % RCHR;
            cp_async16(sstage + 20480 + row * (BN_ * 4) + ch * 16,
                       &Braw[(size_t)(k0 + row) * N_ + n0 + ch * 4]);
        }
    }
    cp_commit();
}

template <int BN_, int NTHR>
__device__ __forceinline__ void conv_b(char* smem, uint32_t raw_off, uint32_t bb_off,
                                       uint32_t bb_half, int tid)
{
    constexpr int B_RL = BN_ + 8;
    constexpr int RC = 8 * BN_;
    #pragma unroll
    for (int i = 0; i < RC / NTHR; i++) {
        int c = tid + i * NTHR;
        float4 v = *reinterpret_cast<const float4*>(smem + raw_off + c * 16);
        int row = c / (BN_ / 4);
        int col = (c % (BN_ / 4)) * 4;
        __nv_bfloat16 h0 = __float2bfloat16(v.x), h1 = __float2bfloat16(v.y);
        __nv_bfloat16 h2 = __float2bfloat16(v.z), h3 = __float2bfloat16(v.w);
        float l0 = v.x - __bfloat162float(h0), l1 = v.y - __bfloat162float(h1);
        float l2 = v.z - __bfloat162float(h2), l3 = v.w - __bfloat162float(h3);
        uint32_t eoff = (uint32_t)(row * B_RL + col) * 2;
        char* hi = smem + bb_off + eoff;
        char* lo = smem + bb_off + bb_half + eoff;
        *reinterpret_cast<__nv_bfloat162*>(hi)     = __halves2bfloat162(h0, h1);
        *reinterpret_cast<__nv_bfloat162*>(hi + 4) = __halves2bfloat162(h2, h3);
        *reinterpret_cast<__nv_bfloat162*>(lo)     =
            __halves2bfloat162(__float2bfloat16(l0), __float2bfloat16(l1));
        *reinterpret_cast<__nv_bfloat162*>(lo + 4) =
            __halves2bfloat162(__float2bfloat16(l2), __float2bfloat16(l3));
    }
}

template <int BN_, int SK, bool HAS_BIAS, int N_, int NWM, int NWN, bool DUAL,
          int MINB, bool FUSE_T>
__global__ void __launch_bounds__(NWM * NWN * 32, MINB) gemm_mma_kernel(
    const __nv_bfloat16* __restrict__ ahi0, const __nv_bfloat16* __restrict__ alo0,
    const float* __restrict__ Braw0, float* __restrict__ C0,
    const __nv_bfloat16* __restrict__ ahi1, const __nv_bfloat16* __restrict__ alo1,
    const float* __restrict__ Braw1, float* __restrict__ C1,
    const float* __restrict__ bias, const float* __restrict__ xsrc)
{
    constexpr int NTHR = NWM * NWN * 32;
    constexpr int WN   = BN_ / NWN;
    constexpr int NT   = WN / 8;
    constexpr int B_RL = BN_ + 8;
    constexpr int STG  = 20480 + 128 * BN_;
    constexpr int OFF_BBc = PSTG * STG;
    constexpr int BB_HALFc = 32 * B_RL * 2;
    constexpr int BB_SZc = 2 * BB_HALFc;
    constexpr int KITERS = Kd / SK / BK;

    extern __shared__ char smem[];
    uint32_t sb = smem_u32(smem);
    const int tid = threadIdx.x, lane = tid & 31, wid = tid >> 5;
    const int warp_m = wid / NWN, warp_n = wid % NWN;
    const int m0 = blockIdx.y * BM, n0 = blockIdx.x * BN_;

    int z = blockIdx.z;
    const __nv_bfloat16* ahi = ahi0;
    const __nv_bfloat16* alo = alo0;
    const float* Braw = Braw0;
    float* C = C0;
    if (DUAL && z >= SK) {
        z -= SK; ahi = ahi1; alo = alo1; Braw = Braw1; C = C1;
    }
    const int kb = z * (Kd / SK);

    float acc[4][NT][4];
    #pragma unroll
    for (int i = 0; i < 4; i++)
        #pragma unroll
        for (int j = 0; j < NT; j++)
            #pragma unroll
            for (int r = 0; r < 4; r++) acc[i][j][r] = 0.f;

    float2 biasv[NT];
    if constexpr (HAS_BIAS) {
        #pragma unroll
        for (int nt = 0; nt < NT; nt++)
            biasv[nt] = *reinterpret_cast<const float2*>(
                &bias[n0 + warp_n * WN + nt * 8 + (lane & 3) * 2]);
    }

    load_grp<BN_, N_, NTHR>(sb, ahi, alo, Braw, m0, n0, kb, tid);
    load_grp<BN_, N_, NTHR>(sb + STG, ahi, alo, Braw, m0, n0, kb + BK, tid);

    cp_wait<1>();
    conv_b<BN_, NTHR>(smem, 20480, OFF_BBc, BB_HALFc, tid);

    const int a_row_in_tile = lane & 15;
    const int a_colblk = (lane >> 4) << 3;
    const int b_row_in_tile = (lane & 7) + ((lane >> 3) & 1) * 8;
    const int b_ncol = warp_n * WN;

    for (int kt = 0; kt < KITERS; kt++) {
        cp_wait<0>();
        __syncthreads();

        if (kt + 2 < KITERS)
            load_grp<BN_, N_, NTHR>(sb + ((kt + 2) % PSTG) * STG, ahi, alo, Braw,
                                    m0, n0, kb + (kt + 2) * BK, tid);
        if (kt + 1 < KITERS)
            conv_b<BN_, NTHR>(smem, ((kt + 1) % PSTG) * STG + 20480,
                              OFF_BBc + ((kt + 1) & 1) * BB_SZc, BB_HALFc, tid);

        uint32_t abase = sb + (kt % PSTG) * STG;
        uint32_t bbase = sb + OFF_BBc + (kt & 1) * BB_SZc;

        #pragma unroll
        for (int ks = 0; ks < 2; ks++) {
            uint32_t af[4][4], bf[NT][2], bl2[NT][2];
            #pragma unroll
            for (int mt = 0; mt < 4; mt++) {
                int row = warp_m * 64 + mt * 16 + a_row_in_tile;
                uint32_t off = (uint32_t)(row * 40 + ks * 16 + a_colblk) * 2;
                ldsm_x4(af[mt][0], af[mt][1], af[mt][2], af[mt][3], abase + off);
            }
            #pragma unroll
            for (int nt = 0; nt < NT; nt++) {
                int krow = ks * 16 + b_row_in_tile;
                uint32_t off = (uint32_t)(krow * B_RL + b_ncol + nt * 8) * 2;
                ldsm_x2_trans(bf[nt][0], bf[nt][1], bbase + off);
            }
            #pragma unroll
            for (int mt = 0; mt < 4; mt++)
                #pragma unroll
                for (int nt = 0; nt < NT; nt++)
                    mma16816(acc[mt][nt], af[mt][0], af[mt][1], af[mt][2], af[mt][3],
                             bf[nt][0], bf[nt][1]);
            #pragma unroll
            for (int nt = 0; nt < NT; nt++) {
                int krow = ks * 16 + b_row_in_tile;
                uint32_t off = (uint32_t)(krow * B_RL + b_ncol + nt * 8) * 2;
                ldsm_x2_trans(bl2[nt][0], bl2[nt][1], bbase + BB_HALFc + off);
            }
            #pragma unroll
            for (int mt = 0; mt < 4; mt++)
                #pragma unroll
                for (int nt = 0; nt < NT; nt++)
                    mma16816(acc[mt][nt], af[mt][0], af[mt][1], af[mt][2], af[mt][3],
                             bl2[nt][0], bl2[nt][1]);
            // reload A-lo into af (A-hi dead)
            #pragma unroll
            for (int mt = 0; mt < 4; mt++) {
                int row = warp_m * 64 + mt * 16 + a_row_in_tile;
                uint32_t off = (uint32_t)(row * 40 + ks * 16 + a_colblk) * 2;
                ldsm_x4(af[mt][0], af[mt][1], af[mt][2], af[mt][3], abase + 10240 + off);
            }
            #pragma unroll
            for (int mt = 0; mt < 4; mt++)
                #pragma unroll
                for (int nt = 0; nt < NT; nt++)
                    mma16816(acc[mt][nt], af[mt][0], af[mt][1], af[mt][2], af[mt][3],
                             bf[nt][0], bf[nt][1]);
        }
    }

    if (FUSE_T && blockIdx.x < (XBN / BN_)) {
        // x_a half: t partials. Each nt fragment = one d, r=0..7.
        float* tpart = (float*)smem;                          // [NWN][128][8]
        float* x_s = (float*)(smem + NWN * 128 * 8 * 4);      // [128][32]
        __syncthreads();
        {
            // load x tile: rows m0..m0+127, d = n0/8 .. +32  (512 threads)
            int d0 = n0 / 8;
            int row = tid >> 2, ch = tid & 3;
            float4 v = *reinterpret_cast<const float4*>(
                &xsrc[(size_t)(m0 + row) * Dd + d0 + ch * 8]);
            float4 v2 = *reinterpret_cast<const float4*>(
                &xsrc[(size_t)(m0 + row) * Dd + d0 + ch * 8 + 4]);
            *reinterpret_cast<float4*>(&x_s[row * 32 + ch * 8]) = v;
            *reinterpret_cast<float4*>(&x_s[row * 32 + ch * 8 + 4]) = v2;
        }
        __syncthreads();

        int r0 = (lane & 3) * 2;
        #pragma unroll
        for (int mt = 0; mt < 4; mt++) {
            int row_a = warp_m * 64 + mt * 16 + (lane >> 2);
            int row_b = row_a + 8;
            float t00 = 0.f, t01 = 0.f, t10 = 0.f, t11 = 0.f;
            #pragma unroll
            for (int nt = 0; nt < NT; nt++) {
                int dl = warp_n * NT + nt;
                float xa = x_s[row_a * 32 + dl];
                float xb = x_s[row_b * 32 + dl];
                float bx = 0.f, by = 0.f;
                if constexpr (HAS_BIAS) { bx = biasv[nt].x; by = biasv[nt].y; }
                t00 += xa * (acc[mt][nt][0] + bx);
                t01 += xa * (acc[mt][nt][1] + by);
                t10 += xb * (acc[mt][nt][2] + bx);
                t11 += xb * (acc[mt][nt][3] + by);
            }
            tpart[(warp_n * 128 + row_a) * 8 + r0]     = t00;
            tpart[(warp_n * 128 + row_a) * 8 + r0 + 1] = t01;
            tpart[(warp_n * 128 + row_b) * 8 + r0]     = t10;
            tpart[(warp_n * 128 + row_b) * 8 + r0 + 1] = t11;
        }
        __syncthreads();
        #pragma unroll
        for (int i = 0; i < 2; i++) {
            int pr = tid + i * NTHR;      // 0..1023
            int row = pr >> 3, r = pr & 7;
            float s = 0.f;
            #pragma unroll
            for (int w = 0; w < NWN; w++)
                s += tpart[(w * 128 + row) * 8 + r];
            g_tp[((size_t)blockIdx.x * Bsz + m0 + row) * Rr + r] = s;
        }
        return;
    }

    // normal / x_b store
    float* Cw;
    if constexpr (SK == 1) {
        Cw = C;
    } else {
        Cw = C + (size_t)z * Bsz * N_;
    }
    int nbase = n0;
    int nstride = N_;
    if constexpr (FUSE_T) { nbase = n0 - XBN; nstride = XBN; }
    #pragma unroll
    for (int mt = 0; mt < 4; mt++) {
        int row0 = m0 + warp_m * 64 + mt * 16 + (lane >> 2);
        #pragma unroll
        for (int nt = 0; nt < NT; nt++) {
            int col = nbase + warp_n * WN + nt * 8 + (lane & 3) * 2;
            float bx = 0.f, by = 0.f;
            if constexpr (HAS_BIAS) { bx = biasv[nt].x; by = biasv[nt].y; }
            float2 v0 = make_float2(acc[mt][nt][0] + bx, acc[mt][nt][1] + by);
            float2 v1 = make_float2(acc[mt][nt][2] + bx, acc[mt][nt][3] + by);
            *reinterpret_cast<float2*>(&Cw[(size_t)row0 * nstride + col]) = v0;
            *reinterpret_cast<float2*>(&Cw[(size_t)(row0 + 8) * nstride + col]) = v1;
        }
    }
}

// ---------------------------------------------------------------------------
// reduce1: h = GELU(sum_z p1[z] + b1) -> bf16 hi/lo. 512 blocks x 2 elems.
// ---------------------------------------------------------------------------
__global__ void __launch_bounds__(256) reduce1_kernel(const float* __restrict__ b1)
{
    int e = (blockIdx.x * 256 + threadIdx.x) * 2;
    float2 p0 = *reinterpret_cast<const float2*>(&g_p1[e]);
    float2 p1v = *reinterpret_cast<const float2*>(&g_p1[1 * (Bsz * Dd) + e]);
    float2 p2 = *reinterpret_cast<const float2*>(&g_p1[2 * (Bsz * Dd) + e]);
    float2 p3 = *reinterpret_cast<const float2*>(&g_p1[3 * (Bsz * Dd) + e]);
    float2 bb = *reinterpret_cast<const float2*>(&b1[e & (Dd - 1)]);
    float u0 = p0.x + p1v.x + p2.x + p3.x + bb.x;
    float u1 = p0.y + p1v.y + p2.y + p3.y + bb.y;
    float g0 = 0.5f * u0 * (1.f + erff(u0 * 0.70710678118654752f));
    float g1 = 0.5f * u1 * (1.f + erff(u1 * 0.70710678118654752f));
    __nv_bfloat16 h0 = __float2bfloat16(g0), h1 = __float2bfloat16(g1);
    *reinterpret_cast<__nv_bfloat162*>(&g_Ahi[e]) = __halves2bfloat162(h0, h1);
    *reinterpret_cast<__nv_bfloat162*>(&g_Alo[e]) = __halves2bfloat162(
        __float2bfloat16(g0 - __bfloat162float(h0)),
        __float2bfloat16(g1 - __bfloat162float(h1)));
}

// ---------------------------------------------------------------------------
// reduce3: out = x + sum_z p3[z] + rank-8 epilogue; one block per b,
// 4 outputs/thread -> many independent float4 loads in flight.
// ---------------------------------------------------------------------------
__global__ void __launch_bounds__(256) reduce3_kernel(
    const float* __restrict__ x, float* __restrict__ out)
{
    int b = blockIdx.x;
    __shared__ float t_s[Rr];
    {
        int p = threadIdx.x & 31, r = threadIdx.x >> 5;
        float v = g_tp[((size_t)p * Bsz + b) * Rr + r];
        #pragma unroll
        for (int o = 16; o; o >>= 1)
            v += __shfl_down_sync(0xFFFFFFFFu, v, o);
        if (p == 0) t_s[r] = v;
    }
    __syncthreads();

    int o = threadIdx.x * 4;
    size_t e = (size_t)b * Dd + o;
    float4 s = *reinterpret_cast<const float4*>(&x[e]);
    float4 q0 = *reinterpret_cast<const float4*>(&g_p3[0 * (Bsz * Dd) + e]);
    float4 q1 = *reinterpret_cast<const float4*>(&g_p3[1 * (Bsz * Dd) + e]);
    float4 q2 = *reinterpret_cast<const float4*>(&g_p3[2 * (Bsz * Dd) + e]);
    float4 q3 = *reinterpret_cast<const float4*>(&g_p3[3 * (Bsz * Dd) + e]);
    const float* wb = &g_w[(size_t)b * XBN + (size_t)o * Rr];
    float4 w[8];
    #pragma unroll
    for (int i = 0; i < 8; i++)
        w[i] = *reinterpret_cast<const float4*>(wb + i * 4);

    float t0 = t_s[0], t1 = t_s[1], t2 = t_s[2], t3 = t_s[3];
    float t4 = t_s[4], t5 = t_s[5], t6 = t_s[6], t7 = t_s[7];
    float lr[4];
    #pragma unroll
    for (int i = 0; i < 4; i++) {
        float4 wa = w[i * 2], wbv = w[i * 2 + 1];
        lr[i] = t0*wa.x + t1*wa.y + t2*wa.z + t3*wa.w
              + t4*wbv.x + t5*wbv.y + t6*wbv.z + t7*wbv.w;
    }
    float4 r;
    r.x = s.x + q0.x + q1.x + q2.x + q3.x + lr[0];
    r.y = s.y + q0.y + q1.y + q2.y + q3.y + lr[1];
    r.z = s.z + q0.z + q1.z + q2.z + q3.z + lr[2];
    r.w = s.w + q0.w + q1.w + q2.w + q3.w + lr[3];
    *reinterpret_cast<float4*>(&out[e]) = r;
}

// ---------------------------------------------------------------------------
extern "C" void kernel_launch(void* const* d_in, const int* in_sizes, int n_in,
                              void* d_out, int out_size)
{
    const float* x    = (const float*)d_in[0];
    const float* ada  = (const float*)d_in[1];
    const float* base = (const float*)d_in[2];
    const float* gam  = (const float*)d_in[3];
    const float* bet  = (const float*)d_in[4];
    const float* W1   = (const float*)d_in[5];
    const float* b1   = (const float*)d_in[6];
    const float* W2   = (const float*)d_in[7];
    const float* b2   = (const float*)d_in[8];
    float* out = (float*)d_out;

    constexpr int SMEM64  = 3 * (20480 + 128 * 64)  + 2 * (2 * 32 * 72 * 2);   // 104448
    constexpr int SMEM256 = 3 * (20480 + 128 * 256) + 2 * (2 * 32 * 264 * 2);  // 227328

    float *w_p, *p1_p, *p3_p;
    __nv_bfloat16 *chi_p, *clo_p, *ahi_p, *alo_p, *xhi_p, *xlo_p;
    cudaGetSymbolAddress((void**)&w_p,  g_w);
    cudaGetSymbolAddress((void**)&p1_p, g_p1);
    cudaGetSymbolAddress((void**)&p3_p, g_p3);
    cudaGetSymbolAddress((void**)&chi_p, g_Chi);
    cudaGetSymbolAddress((void**)&clo_p, g_Clo);
    cudaGetSymbolAddress((void**)&ahi_p, g_Ahi);
    cudaGetSymbolAddress((void**)&alo_p, g_Alo);
    cudaGetSymbolAddress((void**)&xhi_p, g_Xhi);
    cudaGetSymbolAddress((void**)&xlo_p, g_Xlo);

    auto k13 = gemm_mma_kernel<64, 4, false, 1024, 2, 4, true, 2, false>;
    auto k2  = gemm_mma_kernel<256, 1, true, 16384, 2, 8, false, 1, true>;

    cudaFuncSetAttribute((const void*)k13,
                         cudaFuncAttributeMaxDynamicSharedMemorySize, SMEM64);
    cudaFuncSetAttribute((const void*)k2,
                         cudaFuncAttributeMaxDynamicSharedMemorySize, SMEM256);

    // prepass: LN (256 blocks) + x split (512 blocks)
    prepass_kernel<<<768, 256>>>(ada, gam, bet, x);

    // GEMM1 + GEMM3 fused: z<4 -> cond@W1 partials, z>=4 -> x@base partials
    k13<<<dim3(16, 2, 8), 256, SMEM64>>>(
        chi_p, clo_p, W1, p1_p,
        xhi_p, xlo_p, base, p3_p, nullptr, nullptr);

    // reduce1: + b1, GELU, split -> g_Ahi/g_Alo
    reduce1_kernel<<<(Bsz * Kd) / 512, 256>>>(b1);

    // GEMM2: single wave (128 CTAs, 512 thr); x_a half -> t partials, x_b -> g_w
    k2<<<dim3(W2N / 256, Bsz / BM, 1), 512, SMEM256>>>(
        ahi_p, alo_p, W2, w_p,
        nullptr, nullptr, nullptr, nullptr, b2, x);

    // final epilogue
    reduce3_kernel<<<Bsz, 256>>>(x, out);
}

// round 13
// speedup vs baseline: 1.3019x; 1.0178x over previous
#include <cuda_runtime.h>
#include <cuda_bf16.h>
#include <math.h>
#include <cstdint>

// ---------------------------------------------------------------------------
// AdaLoRAWithBase restructured:
//   out = x + x@base + sum_r t[b,r] * x_b[b,:,r],  t[b,r] = sum_c x[b,c]*x_a[b,c,r]
//   [x_a|x_b] = GELU(LN(ada)@W1+b1) @ W2 + b2
// R13: R12 core; gemm3 (x@base) drops the x_lo pass (2-pass split) since its
// output is a small fraction of out (error contribution ~2e-4 << 1e-3).
// gemm1/gemm2 stay 3-pass (they feed the dominant lora term).
// ---------------------------------------------------------------------------

namespace {
constexpr int Bsz = 256;
constexpr int Dd  = 1024;
constexpr int Aa  = 1024;
constexpr int Rr  = 8;
constexpr int W2N = Dd * Rr * 2;     // 16384
constexpr int XBN = Dd * Rr;         // 8192 (x_b width)
constexpr int Kd  = 1024;

constexpr int BM = 128, BK = 32;
constexpr int PSTG = 3;
constexpr int A_ROWB = 80;           // bytes per A smem row (40 bf16)
}

// Scratch (device globals)
__device__ __align__(16) float g_w[(size_t)Bsz * XBN];   // 8 MB (x_b only)
__device__ __align__(16) float g_tp[32 * Bsz * Rr];      // per-CTA t partials
__device__ __align__(16) float g_p1[4 * Bsz * Dd];
__device__ __align__(16) float g_p3[4 * Bsz * Dd];
__device__ __align__(16) __nv_bfloat16 g_Chi[Bsz * Kd];
__device__ __align__(16) __nv_bfloat16 g_Clo[Bsz * Kd];
__device__ __align__(16) __nv_bfloat16 g_Ahi[Bsz * Kd];
__device__ __align__(16) __nv_bfloat16 g_Alo[Bsz * Kd];
__device__ __align__(16) __nv_bfloat16 g_Xhi[Bsz * Kd];
__device__ __align__(16) __nv_bfloat16 g_Xlo[Bsz * Kd];  // unused (2-pass gemm3)

// ---------------------------------------------------------------------------
// PTX helpers (baseline sm_80+)
// ---------------------------------------------------------------------------
__device__ __forceinline__ uint32_t smem_u32(const void* p) {
    uint32_t a;
    asm("{ .reg .u64 t; cvta.to.shared.u64 t, %1; cvt.u32.u64 %0, t; }" : "=r"(a) : "l"(p));
    return a;
}
__device__ __forceinline__ void cp_async16(uint32_t saddr, const void* gaddr) {
    asm volatile("cp.async.cg.shared.global [%0], [%1], 16;" :: "r"(saddr), "l"(gaddr) : "memory");
}
__device__ __forceinline__ void cp_commit() {
    asm volatile("cp.async.commit_group;" ::: "memory");
}
template <int N>
__device__ __forceinline__ void cp_wait() {
    asm volatile("cp.async.wait_group %0;" :: "n"(N) : "memory");
}
__device__ __forceinline__ void ldsm_x4(uint32_t& r0, uint32_t& r1, uint32_t& r2, uint32_t& r3,
                                        uint32_t addr) {
    asm volatile("ldmatrix.sync.aligned.m8n8.x4.shared.b16 {%0,%1,%2,%3}, [%4];"
                 : "=r"(r0), "=r"(r1), "=r"(r2), "=r"(r3) : "r"(addr));
}
__device__ __forceinline__ void ldsm_x2_trans(uint32_t& r0, uint32_t& r1, uint32_t addr) {
    asm volatile("ldmatrix.sync.aligned.m8n8.x2.trans.shared.b16 {%0,%1}, [%2];"
                 : "=r"(r0), "=r"(r1) : "r"(addr));
}
__device__ __forceinline__ void mma16816(float* c, uint32_t a0, uint32_t a1, uint32_t a2,
                                         uint32_t a3, uint32_t b0, uint32_t b1) {
    asm volatile(
        "mma.sync.aligned.m16n8k16.row.col.f32.bf16.bf16.f32 "
        "{%0,%1,%2,%3},{%4,%5,%6,%7},{%8,%9},{%0,%1,%2,%3};"
        : "+f"(c[0]), "+f"(c[1]), "+f"(c[2]), "+f"(c[3])
        : "r"(a0), "r"(a1), "r"(a2), "r"(a3), "r"(b0), "r"(b1));
}

// ---------------------------------------------------------------------------
// Merged pre-pass: blocks [0,256) do LayerNorm rows; blocks [256,768) split x
// (hi only; gemm3 is 2-pass and never reads x_lo).
// ---------------------------------------------------------------------------
__global__ void __launch_bounds__(256) prepass_kernel(
    const float* __restrict__ ada, const float* __restrict__ gamma,
    const float* __restrict__ beta, const float* __restrict__ x)
{
    if (blockIdx.x < 256) {
        int b = blockIdx.x;
        const float* row = ada + (size_t)b * Aa;
        float s = 0.f, s2 = 0.f;
        for (int i = threadIdx.x; i < Aa; i += blockDim.x) {
            float v = row[i]; s += v; s2 += v * v;
        }
        #pragma unroll
        for (int o = 16; o; o >>= 1) {
            s  += __shfl_down_sync(0xFFFFFFFFu, s,  o);
            s2 += __shfl_down_sync(0xFFFFFFFFu, s2, o);
        }
        __shared__ float red0[8], red1[8], mv[2];
        int wid = threadIdx.x >> 5, lid = threadIdx.x & 31;
        if (lid == 0) { red0[wid] = s; red1[wid] = s2; }
        __syncthreads();
        if (threadIdx.x == 0) {
            float ts = 0.f, ts2 = 0.f;
            #pragma unroll
            for (int i = 0; i < 8; i++) { ts += red0[i]; ts2 += red1[i]; }
            float mu = ts * (1.f / Aa);
            float var = ts2 * (1.f / Aa) - mu * mu;
            mv[0] = mu; mv[1] = rsqrtf(var + 1e-5f);
        }
        __syncthreads();
        float mu = mv[0], rs = mv[1];
        for (int i = threadIdx.x; i < Aa; i += blockDim.x) {
            float v = (row[i] - mu) * rs * gamma[i] + beta[i];
            __nv_bfloat16 hi = __float2bfloat16(v);
            g_Chi[(size_t)b * Aa + i] = hi;
            g_Clo[(size_t)b * Aa + i] = __float2bfloat16(v - __bfloat162float(hi));
        }
    } else {
        int i = ((blockIdx.x - 256) * 256 + threadIdx.x) * 2;
        float v0 = x[i], v1 = x[i + 1];
        *reinterpret_cast<__nv_bfloat162*>(&g_Xhi[i]) =
            __halves2bfloat162(__float2bfloat16(v0), __float2bfloat16(v1));
    }
}

// ---------------------------------------------------------------------------
// Unified bf16 hi/lo MMA GEMM, fused fp32 B conversion, PSTG=3.
// 3-pass (hi*hi + hi*lo + lo*hi) by default; per-problem 2-pass (drop A-lo).
// FUSE_T: x_a-half CTAs (blockIdx.x < XBN/BN_) compute t partials.
// ---------------------------------------------------------------------------
template <int BN_, int N_, int NTHR>
__device__ __forceinline__ void load_grp(
    uint32_t sstage, const __nv_bfloat16* __restrict__ ahi,
    const __nv_bfloat16* __restrict__ alo, const float* __restrict__ Braw,
    int m0, int n0, int k0, int tid, bool load_alo)
{
    constexpr int RCHR = BN_ / 4;
    constexpr int TOT = 1024 + 8 * BN_;
    #pragma unroll
    for (int it = 0; it < TOT / NTHR; it++) {
        int idx = tid + it * NTHR;
        if (idx < 512) {
            int row = idx >> 2, ch = idx & 3;
            cp_async16(sstage + row * A_ROWB + ch * 16,
                       &ahi[(size_t)(m0 + row) * Kd + k0 + ch * 8]);
        } else if (idx < 1024) {
            if (load_alo) {
                int l = idx - 512, row = l >> 2, ch = l & 3;
                cp_async16(sstage + 10240 + row * A_ROWB + ch * 16,
                           &alo[(size_t)(m0 + row) * Kd + k0 + ch * 8]);
            }
        } else {
            int l = idx - 1024;
            int row = l / RCHR, ch = l % RCHR;
            cp_async16(sstage + 20480 + row * (BN_ * 4) + ch * 16,
                       &Braw[(size_t)(k0 + row) * N_ + n0 + ch * 4]);
        }
    }
    cp_commit();
}

template <int BN_, int NTHR>
__device__ __forceinline__ void conv_b(char* smem, uint32_t raw_off, uint32_t bb_off,
                                       uint32_t bb_half, int tid)
{
    constexpr int B_RL = BN_ + 8;
    constexpr int RC = 8 * BN_;
    #pragma unroll
    for (int i = 0; i < RC / NTHR; i++) {
        int c = tid + i * NTHR;
        float4 v = *reinterpret_cast<const float4*>(smem + raw_off + c * 16);
        int row = c / (BN_ / 4);
        int col = (c % (BN_ / 4)) * 4;
        __nv_bfloat16 h0 = __float2bfloat16(v.x), h1 = __float2bfloat16(v.y);
        __nv_bfloat16 h2 = __float2bfloat16(v.z), h3 = __float2bfloat16(v.w);
        float l0 = v.x - __bfloat162float(h0), l1 = v.y - __bfloat162float(h1);
        float l2 = v.z - __bfloat162float(h2), l3 = v.w - __bfloat162float(h3);
        uint32_t eoff = (uint32_t)(row * B_RL + col) * 2;
        char* hi = smem + bb_off + eoff;
        char* lo = smem + bb_off + bb_half + eoff;
        *reinterpret_cast<__nv_bfloat162*>(hi)     = __halves2bfloat162(h0, h1);
        *reinterpret_cast<__nv_bfloat162*>(hi + 4) = __halves2bfloat162(h2, h3);
        *reinterpret_cast<__nv_bfloat162*>(lo)     =
            __halves2bfloat162(__float2bfloat16(l0), __float2bfloat16(l1));
        *reinterpret_cast<__nv_bfloat162*>(lo + 4) =
            __halves2bfloat162(__float2bfloat16(l2), __float2bfloat16(l3));
    }
}

template <int BN_, int SK, bool HAS_BIAS, int N_, int NWM, int NWN, bool DUAL,
          int MINB, bool FUSE_T, bool TWOPASS1>
__global__ void __launch_bounds__(NWM * NWN * 32, MINB) gemm_mma_kernel(
    const __nv_bfloat16* __restrict__ ahi0, const __nv_bfloat16* __restrict__ alo0,
    const float* __restrict__ Braw0, float* __restrict__ C0,
    const __nv_bfloat16* __restrict__ ahi1, const __nv_bfloat16* __restrict__ alo1,
    const float* __restrict__ Braw1, float* __restrict__ C1,
    const float* __restrict__ bias, const float* __restrict__ xsrc)
{
    constexpr int NTHR = NWM * NWN * 32;
    constexpr int WN   = BN_ / NWN;
    constexpr int NT   = WN / 8;
    constexpr int B_RL = BN_ + 8;
    constexpr int STG  = 20480 + 128 * BN_;
    constexpr int OFF_BBc = PSTG * STG;
    constexpr int BB_HALFc = 32 * B_RL * 2;
    constexpr int BB_SZc = 2 * BB_HALFc;
    constexpr int KITERS = Kd / SK / BK;

    extern __shared__ char smem[];
    uint32_t sb = smem_u32(smem);
    const int tid = threadIdx.x, lane = tid & 31, wid = tid >> 5;
    const int warp_m = wid / NWN, warp_n = wid % NWN;
    const int m0 = blockIdx.y * BM, n0 = blockIdx.x * BN_;

    int z = blockIdx.z;
    const __nv_bfloat16* ahi = ahi0;
    const __nv_bfloat16* alo = alo0;
    const float* Braw = Braw0;
    float* C = C0;
    // 2-pass (drop A-lo) for problem-1 side when TWOPASS1
    const bool threep = !(TWOPASS1 && DUAL && blockIdx.z >= SK);
    if (DUAL && z >= SK) {
        z -= SK; ahi = ahi1; alo = alo1; Braw = Braw1; C = C1;
    }
    const int kb = z * (Kd / SK);

    float acc[4][NT][4];
    #pragma unroll
    for (int i = 0; i < 4; i++)
        #pragma unroll
        for (int j = 0; j < NT; j++)
            #pragma unroll
            for (int r = 0; r < 4; r++) acc[i][j][r] = 0.f;

    float2 biasv[NT];
    if constexpr (HAS_BIAS) {
        #pragma unroll
        for (int nt = 0; nt < NT; nt++)
            biasv[nt] = *reinterpret_cast<const float2*>(
                &bias[n0 + warp_n * WN + nt * 8 + (lane & 3) * 2]);
    }

    load_grp<BN_, N_, NTHR>(sb, ahi, alo, Braw, m0, n0, kb, tid, threep);
    load_grp<BN_, N_, NTHR>(sb + STG, ahi, alo, Braw, m0, n0, kb + BK, tid, threep);

    cp_wait<1>();
    conv_b<BN_, NTHR>(smem, 20480, OFF_BBc, BB_HALFc, tid);

    const int a_row_in_tile = lane & 15;
    const int a_colblk = (lane >> 4) << 3;
    const int b_row_in_tile = (lane & 7) + ((lane >> 3) & 1) * 8;
    const int b_ncol = warp_n * WN;

    for (int kt = 0; kt < KITERS; kt++) {
        cp_wait<0>();
        __syncthreads();

        if (kt + 2 < KITERS)
            load_grp<BN_, N_, NTHR>(sb + ((kt + 2) % PSTG) * STG, ahi, alo, Braw,
                                    m0, n0, kb + (kt + 2) * BK, tid, threep);
        if (kt + 1 < KITERS)
            conv_b<BN_, NTHR>(smem, ((kt + 1) % PSTG) * STG + 20480,
                              OFF_BBc + ((kt + 1) & 1) * BB_SZc, BB_HALFc, tid);

        uint32_t abase = sb + (kt % PSTG) * STG;
        uint32_t bbase = sb + OFF_BBc + (kt & 1) * BB_SZc;

        #pragma unroll
        for (int ks = 0; ks < 2; ks++) {
            uint32_t af[4][4], bf[NT][2], bl2[NT][2];
            #pragma unroll
            for (int mt = 0; mt < 4; mt++) {
                int row = warp_m * 64 + mt * 16 + a_row_in_tile;
                uint32_t off = (uint32_t)(row * 40 + ks * 16 + a_colblk) * 2;
                ldsm_x4(af[mt][0], af[mt][1], af[mt][2], af[mt][3], abase + off);
            }
            #pragma unroll
            for (int nt = 0; nt < NT; nt++) {
                int krow = ks * 16 + b_row_in_tile;
                uint32_t off = (uint32_t)(krow * B_RL + b_ncol + nt * 8) * 2;
                ldsm_x2_trans(bf[nt][0], bf[nt][1], bbase + off);
            }
            #pragma unroll
            for (int mt = 0; mt < 4; mt++)
                #pragma unroll
                for (int nt = 0; nt < NT; nt++)
                    mma16816(acc[mt][nt], af[mt][0], af[mt][1], af[mt][2], af[mt][3],
                             bf[nt][0], bf[nt][1]);
            #pragma unroll
            for (int nt = 0; nt < NT; nt++) {
                int krow = ks * 16 + b_row_in_tile;
                uint32_t off = (uint32_t)(krow * B_RL + b_ncol + nt * 8) * 2;
                ldsm_x2_trans(bl2[nt][0], bl2[nt][1], bbase + BB_HALFc + off);
            }
            #pragma unroll
            for (int mt = 0; mt < 4; mt++)
                #pragma unroll
                for (int nt = 0; nt < NT; nt++)
                    mma16816(acc[mt][nt], af[mt][0], af[mt][1], af[mt][2], af[mt][3],
                             bl2[nt][0], bl2[nt][1]);
            // pass 3: A-lo x B-hi (skipped for 2-pass problems)
            if (threep) {
                #pragma unroll
                for (int mt = 0; mt < 4; mt++) {
                    int row = warp_m * 64 + mt * 16 + a_row_in_tile;
                    uint32_t off = (uint32_t)(row * 40 + ks * 16 + a_colblk) * 2;
                    ldsm_x4(af[mt][0], af[mt][1], af[mt][2], af[mt][3],
                            abase + 10240 + off);
                }
                #pragma unroll
                for (int mt = 0; mt < 4; mt++)
                    #pragma unroll
                    for (int nt = 0; nt < NT; nt++)
                        mma16816(acc[mt][nt], af[mt][0], af[mt][1], af[mt][2], af[mt][3],
                                 bf[nt][0], bf[nt][1]);
            }
        }
    }

    if (FUSE_T && blockIdx.x < (XBN / BN_)) {
        // x_a half: t partials. Each nt fragment = one d, r=0..7.
        float* tpart = (float*)smem;                          // [NWN][128][8]
        float* x_s = (float*)(smem + NWN * 128 * 8 * 4);      // [128][32]
        __syncthreads();
        {
            // load x tile: rows m0..m0+127, d = n0/8 .. +32  (512 threads)
            int d0 = n0 / 8;
            int row = tid >> 2, ch = tid & 3;
            float4 v = *reinterpret_cast<const float4*>(
                &xsrc[(size_t)(m0 + row) * Dd + d0 + ch * 8]);
            float4 v2 = *reinterpret_cast<const float4*>(
                &xsrc[(size_t)(m0 + row) * Dd + d0 + ch * 8 + 4]);
            *reinterpret_cast<float4*>(&x_s[row * 32 + ch * 8]) = v;
            *reinterpret_cast<float4*>(&x_s[row * 32 + ch * 8 + 4]) = v2;
        }
        __syncthreads();

        int r0 = (lane & 3) * 2;
        #pragma unroll
        for (int mt = 0; mt < 4; mt++) {
            int row_a = warp_m * 64 + mt * 16 + (lane >> 2);
            int row_b = row_a + 8;
            float t00 = 0.f, t01 = 0.f, t10 = 0.f, t11 = 0.f;
            #pragma unroll
            for (int nt = 0; nt < NT; nt++) {
                int dl = warp_n * NT + nt;
                float xa = x_s[row_a * 32 + dl];
                float xb = x_s[row_b * 32 + dl];
                float bx = 0.f, by = 0.f;
                if constexpr (HAS_BIAS) { bx = biasv[nt].x; by = biasv[nt].y; }
                t00 += xa * (acc[mt][nt][0] + bx);
                t01 += xa * (acc[mt][nt][1] + by);
                t10 += xb * (acc[mt][nt][2] + bx);
                t11 += xb * (acc[mt][nt][3] + by);
            }
            tpart[(warp_n * 128 + row_a) * 8 + r0]     = t00;
            tpart[(warp_n * 128 + row_a) * 8 + r0 + 1] = t01;
            tpart[(warp_n * 128 + row_b) * 8 + r0]     = t10;
            tpart[(warp_n * 128 + row_b) * 8 + r0 + 1] = t11;
        }
        __syncthreads();
        #pragma unroll
        for (int i = 0; i < 2; i++) {
            int pr = tid + i * NTHR;      // 0..1023
            int row = pr >> 3, r = pr & 7;
            float s = 0.f;
            #pragma unroll
            for (int w = 0; w < NWN; w++)
                s += tpart[(w * 128 + row) * 8 + r];
            g_tp[((size_t)blockIdx.x * Bsz + m0 + row) * Rr + r] = s;
        }
        return;
    }

    // normal / x_b store
    float* Cw;
    if constexpr (SK == 1) {
        Cw = C;
    } else {
        Cw = C + (size_t)z * Bsz * N_;
    }
    int nbase = n0;
    int nstride = N_;
    if constexpr (FUSE_T) { nbase = n0 - XBN; nstride = XBN; }
    #pragma unroll
    for (int mt = 0; mt < 4; mt++) {
        int row0 = m0 + warp_m * 64 + mt * 16 + (lane >> 2);
        #pragma unroll
        for (int nt = 0; nt < NT; nt++) {
            int col = nbase + warp_n * WN + nt * 8 + (lane & 3) * 2;
            float bx = 0.f, by = 0.f;
            if constexpr (HAS_BIAS) { bx = biasv[nt].x; by = biasv[nt].y; }
            float2 v0 = make_float2(acc[mt][nt][0] + bx, acc[mt][nt][1] + by);
            float2 v1 = make_float2(acc[mt][nt][2] + bx, acc[mt][nt][3] + by);
            *reinterpret_cast<float2*>(&Cw[(size_t)row0 * nstride + col]) = v0;
            *reinterpret_cast<float2*>(&Cw[(size_t)(row0 + 8) * nstride + col]) = v1;
        }
    }
}

// ---------------------------------------------------------------------------
// reduce1: h = GELU(sum_z p1[z] + b1) -> bf16 hi/lo. 512 blocks x 2 elems.
// ---------------------------------------------------------------------------
__global__ void __launch_bounds__(256) reduce1_kernel(const float* __restrict__ b1)
{
    int e = (blockIdx.x * 256 + threadIdx.x) * 2;
    float2 p0 = *reinterpret_cast<const float2*>(&g_p1[e]);
    float2 p1v = *reinterpret_cast<const float2*>(&g_p1[1 * (Bsz * Dd) + e]);
    float2 p2 = *reinterpret_cast<const float2*>(&g_p1[2 * (Bsz * Dd) + e]);
    float2 p3 = *reinterpret_cast<const float2*>(&g_p1[3 * (Bsz * Dd) + e]);
    float2 bb = *reinterpret_cast<const float2*>(&b1[e & (Dd - 1)]);
    float u0 = p0.x + p1v.x + p2.x + p3.x + bb.x;
    float u1 = p0.y + p1v.y + p2.y + p3.y + bb.y;
    float g0 = 0.5f * u0 * (1.f + erff(u0 * 0.70710678118654752f));
    float g1 = 0.5f * u1 * (1.f + erff(u1 * 0.70710678118654752f));
    __nv_bfloat16 h0 = __float2bfloat16(g0), h1 = __float2bfloat16(g1);
    *reinterpret_cast<__nv_bfloat162*>(&g_Ahi[e]) = __halves2bfloat162(h0, h1);
    *reinterpret_cast<__nv_bfloat162*>(&g_Alo[e]) = __halves2bfloat162(
        __float2bfloat16(g0 - __bfloat162float(h0)),
        __float2bfloat16(g1 - __bfloat162float(h1)));
}

// ---------------------------------------------------------------------------
// reduce3: out = x + sum_z p3[z] + rank-8 epilogue; one block per b.
// ---------------------------------------------------------------------------
__global__ void __launch_bounds__(256) reduce3_kernel(
    const float* __restrict__ x, float* __restrict__ out)
{
    int b = blockIdx.x;
    __shared__ float t_s[Rr];
    {
        int p = threadIdx.x & 31, r = threadIdx.x >> 5;
        float v = g_tp[((size_t)p * Bsz + b) * Rr + r];
        #pragma unroll
        for (int o = 16; o; o >>= 1)
            v += __shfl_down_sync(0xFFFFFFFFu, v, o);
        if (p == 0) t_s[r] = v;
    }
    __syncthreads();

    int o = threadIdx.x * 4;
    size_t e = (size_t)b * Dd + o;
    float4 s = *reinterpret_cast<const float4*>(&x[e]);
    float4 q0 = *reinterpret_cast<const float4*>(&g_p3[0 * (Bsz * Dd) + e]);
    float4 q1 = *reinterpret_cast<const float4*>(&g_p3[1 * (Bsz * Dd) + e]);
    float4 q2 = *reinterpret_cast<const float4*>(&g_p3[2 * (Bsz * Dd) + e]);
    float4 q3 = *reinterpret_cast<const float4*>(&g_p3[3 * (Bsz * Dd) + e]);
    const float* wb = &g_w[(size_t)b * XBN + (size_t)o * Rr];
    float4 w[8];
    #pragma unroll
    for (int i = 0; i < 8; i++)
        w[i] = *reinterpret_cast<const float4*>(wb + i * 4);

    float t0 = t_s[0], t1 = t_s[1], t2 = t_s[2], t3 = t_s[3];
    float t4 = t_s[4], t5 = t_s[5], t6 = t_s[6], t7 = t_s[7];
    float lr[4];
    #pragma unroll
    for (int i = 0; i < 4; i++) {
        float4 wa = w[i * 2], wbv = w[i * 2 + 1];
        lr[i] = t0*wa.x + t1*wa.y + t2*wa.z + t3*wa.w
              + t4*wbv.x + t5*wbv.y + t6*wbv.z + t7*wbv.w;
    }
    float4 r;
    r.x = s.x + q0.x + q1.x + q2.x + q3.x + lr[0];
    r.y = s.y + q0.y + q1.y + q2.y + q3.y + lr[1];
    r.z = s.z + q0.z + q1.z + q2.z + q3.z + lr[2];
    r.w = s.w + q0.w + q1.w + q2.w + q3.w + lr[3];
    *reinterpret_cast<float4*>(&out[e]) = r;
}

// ---------------------------------------------------------------------------
extern "C" void kernel_launch(void* const* d_in, const int* in_sizes, int n_in,
                              void* d_out, int out_size)
{
    const float* x    = (const float*)d_in[0];
    const float* ada  = (const float*)d_in[1];
    const float* base = (const float*)d_in[2];
    const float* gam  = (const float*)d_in[3];
    const float* bet  = (const float*)d_in[4];
    const float* W1   = (const float*)d_in[5];
    const float* b1   = (const float*)d_in[6];
    const float* W2   = (const float*)d_in[7];
    const float* b2   = (const float*)d_in[8];
    float* out = (float*)d_out;

    constexpr int SMEM64  = 3 * (20480 + 128 * 64)  + 2 * (2 * 32 * 72 * 2);   // 104448
    constexpr int SMEM256 = 3 * (20480 + 128 * 256) + 2 * (2 * 32 * 264 * 2);  // 227328

    float *w_p, *p1_p, *p3_p;
    __nv_bfloat16 *chi_p, *clo_p, *ahi_p, *alo_p, *xhi_p, *xlo_p;
    cudaGetSymbolAddress((void**)&w_p,  g_w);
    cudaGetSymbolAddress((void**)&p1_p, g_p1);
    cudaGetSymbolAddress((void**)&p3_p, g_p3);
    cudaGetSymbolAddress((void**)&chi_p, g_Chi);
    cudaGetSymbolAddress((void**)&clo_p, g_Clo);
    cudaGetSymbolAddress((void**)&ahi_p, g_Ahi);
    cudaGetSymbolAddress((void**)&alo_p, g_Alo);
    cudaGetSymbolAddress((void**)&xhi_p, g_Xhi);
    cudaGetSymbolAddress((void**)&xlo_p, g_Xlo);

    // k13: DUAL; problem 0 = gemm1 (3-pass), problem 1 = gemm3 (2-pass, no A-lo)
    auto k13 = gemm_mma_kernel<64, 4, false, 1024, 2, 4, true, 2, false, true>;
    // gemm2: 3-pass, fused t epilogue
    auto k2  = gemm_mma_kernel<256, 1, true, 16384, 2, 8, false, 1, true, false>;

    cudaFuncSetAttribute((const void*)k13,
                         cudaFuncAttributeMaxDynamicSharedMemorySize, SMEM64);
    cudaFuncSetAttribute((const void*)k2,
                         cudaFuncAttributeMaxDynamicSharedMemorySize, SMEM256);

    // prepass: LN (256 blocks) + x hi-split (512 blocks)
    prepass_kernel<<<768, 256>>>(ada, gam, bet, x);

    // GEMM1 + GEMM3 fused: z<4 -> cond@W1 partials (3-pass),
    //                      z>=4 -> x@base partials (2-pass)
    k13<<<dim3(16, 2, 8), 256, SMEM64>>>(
        chi_p, clo_p, W1, p1_p,
        xhi_p, xlo_p, base, p3_p, nullptr, nullptr);

    // reduce1: + b1, GELU, split -> g_Ahi/g_Alo
    reduce1_kernel<<<(Bsz * Kd) / 512, 256>>>(b1);

    // GEMM2: single wave (128 CTAs, 512 thr); x_a half -> t partials, x_b -> g_w
    k2<<<dim3(W2N / 256, Bsz / BM, 1), 512, SMEM256>>>(
        ahi_p, alo_p, W2, w_p,
        nullptr, nullptr, nullptr, nullptr, b2, x);

    // final epilogue
    reduce3_kernel<<<Bsz, 256>>>(x, out);
}

// round 14
// speedup vs baseline: 1.3229x; 1.0161x over previous
#include <cuda_runtime.h>
#include <cuda_bf16.h>
#include <math.h>
#include <cstdint>

// ---------------------------------------------------------------------------
// AdaLoRAWithBase restructured:
//   out = x + x@base + sum_r t[b,r] * x_b[b,:,r],  t[b,r] = sum_c x[b,c]*x_a[b,c,r]
//   [x_a|x_b] = GELU(LN(ada)@W1+b1) @ W2 + b2
// R14: R13 + issue-slot cuts in the MMA mainloop: B frags via ldmatrix.x4.trans
// (half the B LDSM instructions) and packed cvt.rn.bf16x2 conversion in conv_b.
// ---------------------------------------------------------------------------

namespace {
constexpr int Bsz = 256;
constexpr int Dd  = 1024;
constexpr int Aa  = 1024;
constexpr int Rr  = 8;
constexpr int W2N = Dd * Rr * 2;     // 16384
constexpr int XBN = Dd * Rr;         // 8192 (x_b width)
constexpr int Kd  = 1024;

constexpr int BM = 128, BK = 32;
constexpr int PSTG = 3;
constexpr int A_ROWB = 80;           // bytes per A smem row (40 bf16)
}

// Scratch (device globals)
__device__ __align__(16) float g_w[(size_t)Bsz * XBN];   // 8 MB (x_b only)
__device__ __align__(16) float g_tp[32 * Bsz * Rr];      // per-CTA t partials
__device__ __align__(16) float g_p1[4 * Bsz * Dd];
__device__ __align__(16) float g_p3[4 * Bsz * Dd];
__device__ __align__(16) __nv_bfloat16 g_Chi[Bsz * Kd];
__device__ __align__(16) __nv_bfloat16 g_Clo[Bsz * Kd];
__device__ __align__(16) __nv_bfloat16 g_Ahi[Bsz * Kd];
__device__ __align__(16) __nv_bfloat16 g_Alo[Bsz * Kd];
__device__ __align__(16) __nv_bfloat16 g_Xhi[Bsz * Kd];

// ---------------------------------------------------------------------------
// PTX helpers (baseline sm_80+)
// ---------------------------------------------------------------------------
__device__ __forceinline__ uint32_t smem_u32(const void* p) {
    uint32_t a;
    asm("{ .reg .u64 t; cvta.to.shared.u64 t, %1; cvt.u32.u64 %0, t; }" : "=r"(a) : "l"(p));
    return a;
}
__device__ __forceinline__ void cp_async16(uint32_t saddr, const void* gaddr) {
    asm volatile("cp.async.cg.shared.global [%0], [%1], 16;" :: "r"(saddr), "l"(gaddr) : "memory");
}
__device__ __forceinline__ void cp_commit() {
    asm volatile("cp.async.commit_group;" ::: "memory");
}
template <int N>
__device__ __forceinline__ void cp_wait() {
    asm volatile("cp.async.wait_group %0;" :: "n"(N) : "memory");
}
__device__ __forceinline__ void ldsm_x4(uint32_t& r0, uint32_t& r1, uint32_t& r2, uint32_t& r3,
                                        uint32_t addr) {
    asm volatile("ldmatrix.sync.aligned.m8n8.x4.shared.b16 {%0,%1,%2,%3}, [%4];"
                 : "=r"(r0), "=r"(r1), "=r"(r2), "=r"(r3) : "r"(addr));
}
__device__ __forceinline__ void ldsm_x4_trans(uint32_t& r0, uint32_t& r1, uint32_t& r2,
                                              uint32_t& r3, uint32_t addr) {
    asm volatile("ldmatrix.sync.aligned.m8n8.x4.trans.shared.b16 {%0,%1,%2,%3}, [%4];"
                 : "=r"(r0), "=r"(r1), "=r"(r2), "=r"(r3) : "r"(addr));
}
__device__ __forceinline__ void mma16816(float* c, uint32_t a0, uint32_t a1, uint32_t a2,
                                         uint32_t a3, uint32_t b0, uint32_t b1) {
    asm volatile(
        "mma.sync.aligned.m16n8k16.row.col.f32.bf16.bf16.f32 "
        "{%0,%1,%2,%3},{%4,%5,%6,%7},{%8,%9},{%0,%1,%2,%3};"
        : "+f"(c[0]), "+f"(c[1]), "+f"(c[2]), "+f"(c[3])
        : "r"(a0), "r"(a1), "r"(a2), "r"(a3), "r"(b0), "r"(b1));
}
// pack two fp32 -> bf16x2 (RN); a -> low half, b -> high half
__device__ __forceinline__ uint32_t bf16x2_rn(float a, float b) {
    uint32_t r;
    asm("cvt.rn.bf16x2.f32 %0, %2, %1;" : "=r"(r) : "f"(a), "f"(b));
    return r;
}

// ---------------------------------------------------------------------------
// Merged pre-pass: blocks [0,256) do LayerNorm rows; blocks [256,768) split x
// (hi only; gemm3 is 2-pass and never reads x_lo).
// ---------------------------------------------------------------------------
__global__ void __launch_bounds__(256) prepass_kernel(
    const float* __restrict__ ada, const float* __restrict__ gamma,
    const float* __restrict__ beta, const float* __restrict__ x)
{
    if (blockIdx.x < 256) {
        int b = blockIdx.x;
        const float* row = ada + (size_t)b * Aa;
        float s = 0.f, s2 = 0.f;
        for (int i = threadIdx.x; i < Aa; i += blockDim.x) {
            float v = row[i]; s += v; s2 += v * v;
        }
        #pragma unroll
        for (int o = 16; o; o >>= 1) {
            s  += __shfl_down_sync(0xFFFFFFFFu, s,  o);
            s2 += __shfl_down_sync(0xFFFFFFFFu, s2, o);
        }
        __shared__ float red0[8], red1[8], mv[2];
        int wid = threadIdx.x >> 5, lid = threadIdx.x & 31;
        if (lid == 0) { red0[wid] = s; red1[wid] = s2; }
        __syncthreads();
        if (threadIdx.x == 0) {
            float ts = 0.f, ts2 = 0.f;
            #pragma unroll
            for (int i = 0; i < 8; i++) { ts += red0[i]; ts2 += red1[i]; }
            float mu = ts * (1.f / Aa);
            float var = ts2 * (1.f / Aa) - mu * mu;
            mv[0] = mu; mv[1] = rsqrtf(var + 1e-5f);
        }
        __syncthreads();
        float mu = mv[0], rs = mv[1];
        for (int i = threadIdx.x; i < Aa; i += blockDim.x) {
            float v = (row[i] - mu) * rs * gamma[i] + beta[i];
            __nv_bfloat16 hi = __float2bfloat16(v);
            g_Chi[(size_t)b * Aa + i] = hi;
            g_Clo[(size_t)b * Aa + i] = __float2bfloat16(v - __bfloat162float(hi));
        }
    } else {
        int i = ((blockIdx.x - 256) * 256 + threadIdx.x) * 2;
        float v0 = x[i], v1 = x[i + 1];
        *reinterpret_cast<__nv_bfloat162*>(&g_Xhi[i]) =
            __halves2bfloat162(__float2bfloat16(v0), __float2bfloat16(v1));
    }
}

// ---------------------------------------------------------------------------
// Unified bf16 hi/lo MMA GEMM, fused fp32 B conversion, PSTG=3.
// 3-pass by default; per-problem 2-pass (drop A-lo).
// FUSE_T: x_a-half CTAs (blockIdx.x < XBN/BN_) compute t partials.
// ---------------------------------------------------------------------------
template <int BN_, int N_, int NTHR>
__device__ __forceinline__ void load_grp(
    uint32_t sstage, const __nv_bfloat16* __restrict__ ahi,
    const __nv_bfloat16* __restrict__ alo, const float* __restrict__ Braw,
    int m0, int n0, int k0, int tid, bool load_alo)
{
    constexpr int RCHR = BN_ / 4;
    constexpr int TOT = 1024 + 8 * BN_;
    #pragma unroll
    for (int it = 0; it < TOT / NTHR; it++) {
        int idx = tid + it * NTHR;
        if (idx < 512) {
            int row = idx >> 2, ch = idx & 3;
            cp_async16(sstage + row * A_ROWB + ch * 16,
                       &ahi[(size_t)(m0 + row) * Kd + k0 + ch * 8]);
        } else if (idx < 1024) {
            if (load_alo) {
                int l = idx - 512, row = l >> 2, ch = l & 3;
                cp_async16(sstage + 10240 + row * A_ROWB + ch * 16,
                           &alo[(size_t)(m0 + row) * Kd + k0 + ch * 8]);
            }
        } else {
            int l = idx - 1024;
            int row = l / RCHR, ch = l % RCHR;
            cp_async16(sstage + 20480 + row * (BN_ * 4) + ch * 16,
                       &Braw[(size_t)(k0 + row) * N_ + n0 + ch * 4]);
        }
    }
    cp_commit();
}

template <int BN_, int NTHR>
__device__ __forceinline__ void conv_b(char* smem, uint32_t raw_off, uint32_t bb_off,
                                       uint32_t bb_half, int tid)
{
    constexpr int B_RL = BN_ + 8;
    constexpr int RC = 8 * BN_;
    #pragma unroll
    for (int i = 0; i < RC / NTHR; i++) {
        int c = tid + i * NTHR;
        float4 v = *reinterpret_cast<const float4*>(smem + raw_off + c * 16);
        int row = c / (BN_ / 4);
        int col = (c % (BN_ / 4)) * 4;
        uint32_t hi01 = bf16x2_rn(v.x, v.y);
        uint32_t hi23 = bf16x2_rn(v.z, v.w);
        float h0 = __uint_as_float(hi01 << 16);
        float h1 = __uint_as_float(hi01 & 0xFFFF0000u);
        float h2 = __uint_as_float(hi23 << 16);
        float h3 = __uint_as_float(hi23 & 0xFFFF0000u);
        uint32_t lo01 = bf16x2_rn(v.x - h0, v.y - h1);
        uint32_t lo23 = bf16x2_rn(v.z - h2, v.w - h3);
        uint32_t eoff = (uint32_t)(row * B_RL + col) * 2;
        *reinterpret_cast<uint2*>(smem + bb_off + eoff)           = make_uint2(hi01, hi23);
        *reinterpret_cast<uint2*>(smem + bb_off + bb_half + eoff) = make_uint2(lo01, lo23);
    }
}

template <int BN_, int SK, bool HAS_BIAS, int N_, int NWM, int NWN, bool DUAL,
          int MINB, bool FUSE_T, bool TWOPASS1>
__global__ void __launch_bounds__(NWM * NWN * 32, MINB) gemm_mma_kernel(
    const __nv_bfloat16* __restrict__ ahi0, const __nv_bfloat16* __restrict__ alo0,
    const float* __restrict__ Braw0, float* __restrict__ C0,
    const __nv_bfloat16* __restrict__ ahi1, const __nv_bfloat16* __restrict__ alo1,
    const float* __restrict__ Braw1, float* __restrict__ C1,
    const float* __restrict__ bias, const float* __restrict__ xsrc)
{
    constexpr int NTHR = NWM * NWN * 32;
    constexpr int WN   = BN_ / NWN;
    constexpr int NT   = WN / 8;
    constexpr int B_RL = BN_ + 8;
    constexpr int STG  = 20480 + 128 * BN_;
    constexpr int OFF_BBc = PSTG * STG;
    constexpr int BB_HALFc = 32 * B_RL * 2;
    constexpr int BB_SZc = 2 * BB_HALFc;
    constexpr int KITERS = Kd / SK / BK;

    extern __shared__ char smem[];
    uint32_t sb = smem_u32(smem);
    const int tid = threadIdx.x, lane = tid & 31, wid = tid >> 5;
    const int warp_m = wid / NWN, warp_n = wid % NWN;
    const int m0 = blockIdx.y * BM, n0 = blockIdx.x * BN_;

    int z = blockIdx.z;
    const __nv_bfloat16* ahi = ahi0;
    const __nv_bfloat16* alo = alo0;
    const float* Braw = Braw0;
    float* C = C0;
    const bool threep = !(TWOPASS1 && DUAL && blockIdx.z >= SK);
    if (DUAL && z >= SK) {
        z -= SK; ahi = ahi1; alo = alo1; Braw = Braw1; C = C1;
    }
    const int kb = z * (Kd / SK);

    float acc[4][NT][4];
    #pragma unroll
    for (int i = 0; i < 4; i++)
        #pragma unroll
        for (int j = 0; j < NT; j++)
            #pragma unroll
            for (int r = 0; r < 4; r++) acc[i][j][r] = 0.f;

    float2 biasv[NT];
    if constexpr (HAS_BIAS) {
        #pragma unroll
        for (int nt = 0; nt < NT; nt++)
            biasv[nt] = *reinterpret_cast<const float2*>(
                &bias[n0 + warp_n * WN + nt * 8 + (lane & 3) * 2]);
    }

    load_grp<BN_, N_, NTHR>(sb, ahi, alo, Braw, m0, n0, kb, tid, threep);
    load_grp<BN_, N_, NTHR>(sb + STG, ahi, alo, Braw, m0, n0, kb + BK, tid, threep);

    cp_wait<1>();
    conv_b<BN_, NTHR>(smem, 20480, OFF_BBc, BB_HALFc, tid);

    const int a_row_in_tile = lane & 15;
    const int a_colblk = (lane >> 4) << 3;
    // B x4.trans: lanes 0-7 -> (k0-7, col), 8-15 -> (k8-15, col),
    //             16-23 -> (k0-7, col+8), 24-31 -> (k8-15, col+8)
    const int b_krow = (lane & 7) + ((lane >> 3) & 1) * 8;
    const int b_cofs = warp_n * WN + ((lane >> 4) & 1) * 8;

    for (int kt = 0; kt < KITERS; kt++) {
        cp_wait<0>();
        __syncthreads();

        if (kt + 2 < KITERS)
            load_grp<BN_, N_, NTHR>(sb + ((kt + 2) % PSTG) * STG, ahi, alo, Braw,
                                    m0, n0, kb + (kt + 2) * BK, tid, threep);
        if (kt + 1 < KITERS)
            conv_b<BN_, NTHR>(smem, ((kt + 1) % PSTG) * STG + 20480,
                              OFF_BBc + ((kt + 1) & 1) * BB_SZc, BB_HALFc, tid);

        uint32_t abase = sb + (kt % PSTG) * STG;
        uint32_t bbase = sb + OFF_BBc + (kt & 1) * BB_SZc;

        #pragma unroll
        for (int ks = 0; ks < 2; ks++) {
            uint32_t af[4][4], bf[NT][2], bl2[NT][2];
            #pragma unroll
            for (int mt = 0; mt < 4; mt++) {
                int row = warp_m * 64 + mt * 16 + a_row_in_tile;
                uint32_t off = (uint32_t)(row * 40 + ks * 16 + a_colblk) * 2;
                ldsm_x4(af[mt][0], af[mt][1], af[mt][2], af[mt][3], abase + off);
            }
            #pragma unroll
            for (int ntp = 0; ntp < NT / 2; ntp++) {
                uint32_t off = (uint32_t)((ks * 16 + b_krow) * B_RL + b_cofs + ntp * 16) * 2;
                ldsm_x4_trans(bf[2*ntp][0], bf[2*ntp][1], bf[2*ntp+1][0], bf[2*ntp+1][1],
                              bbase + off);
            }
            #pragma unroll
            for (int mt = 0; mt < 4; mt++)
                #pragma unroll
                for (int nt = 0; nt < NT; nt++)
                    mma16816(acc[mt][nt], af[mt][0], af[mt][1], af[mt][2], af[mt][3],
                             bf[nt][0], bf[nt][1]);
            #pragma unroll
            for (int ntp = 0; ntp < NT / 2; ntp++) {
                uint32_t off = (uint32_t)((ks * 16 + b_krow) * B_RL + b_cofs + ntp * 16) * 2;
                ldsm_x4_trans(bl2[2*ntp][0], bl2[2*ntp][1], bl2[2*ntp+1][0], bl2[2*ntp+1][1],
                              bbase + BB_HALFc + off);
            }
            #pragma unroll
            for (int mt = 0; mt < 4; mt++)
                #pragma unroll
                for (int nt = 0; nt < NT; nt++)
                    mma16816(acc[mt][nt], af[mt][0], af[mt][1], af[mt][2], af[mt][3],
                             bl2[nt][0], bl2[nt][1]);
            // pass 3: A-lo x B-hi (skipped for 2-pass problems)
            if (threep) {
                #pragma unroll
                for (int mt = 0; mt < 4; mt++) {
                    int row = warp_m * 64 + mt * 16 + a_row_in_tile;
                    uint32_t off = (uint32_t)(row * 40 + ks * 16 + a_colblk) * 2;
                    ldsm_x4(af[mt][0], af[mt][1], af[mt][2], af[mt][3],
                            abase + 10240 + off);
                }
                #pragma unroll
                for (int mt = 0; mt < 4; mt++)
                    #pragma unroll
                    for (int nt = 0; nt < NT; nt++)
                        mma16816(acc[mt][nt], af[mt][0], af[mt][1], af[mt][2], af[mt][3],
                                 bf[nt][0], bf[nt][1]);
            }
        }
    }

    if (FUSE_T && blockIdx.x < (XBN / BN_)) {
        // x_a half: t partials. Each nt fragment = one d, r=0..7.
        float* tpart = (float*)smem;                          // [NWN][128][8]
        float* x_s = (float*)(smem + NWN * 128 * 8 * 4);      // [128][32]
        __syncthreads();
        {
            // load x tile: rows m0..m0+127, d = n0/8 .. +32  (512 threads)
            int d0 = n0 / 8;
            int row = tid >> 2, ch = tid & 3;
            float4 v = *reinterpret_cast<const float4*>(
                &xsrc[(size_t)(m0 + row) * Dd + d0 + ch * 8]);
            float4 v2 = *reinterpret_cast<const float4*>(
                &xsrc[(size_t)(m0 + row) * Dd + d0 + ch * 8 + 4]);
            *reinterpret_cast<float4*>(&x_s[row * 32 + ch * 8]) = v;
            *reinterpret_cast<float4*>(&x_s[row * 32 + ch * 8 + 4]) = v2;
        }
        __syncthreads();

        int r0 = (lane & 3) * 2;
        #pragma unroll
        for (int mt = 0; mt < 4; mt++) {
            int row_a = warp_m * 64 + mt * 16 + (lane >> 2);
            int row_b = row_a + 8;
            float t00 = 0.f, t01 = 0.f, t10 = 0.f, t11 = 0.f;
            #pragma unroll
            for (int nt = 0; nt < NT; nt++) {
                int dl = warp_n * NT + nt;
                float xa = x_s[row_a * 32 + dl];
                float xb = x_s[row_b * 32 + dl];
                float bx = 0.f, by = 0.f;
                if constexpr (HAS_BIAS) { bx = biasv[nt].x; by = biasv[nt].y; }
                t00 += xa * (acc[mt][nt][0] + bx);
                t01 += xa * (acc[mt][nt][1] + by);
                t10 += xb * (acc[mt][nt][2] + bx);
                t11 += xb * (acc[mt][nt][3] + by);
            }
            tpart[(warp_n * 128 + row_a) * 8 + r0]     = t00;
            tpart[(warp_n * 128 + row_a) * 8 + r0 + 1] = t01;
            tpart[(warp_n * 128 + row_b) * 8 + r0]     = t10;
            tpart[(warp_n * 128 + row_b) * 8 + r0 + 1] = t11;
        }
        __syncthreads();
        #pragma unroll
        for (int i = 0; i < 2; i++) {
            int pr = tid + i * NTHR;      // 0..1023
            int row = pr >> 3, r = pr & 7;
            float s = 0.f;
            #pragma unroll
            for (int w = 0; w < NWN; w++)
                s += tpart[(w * 128 + row) * 8 + r];
            g_tp[((size_t)blockIdx.x * Bsz + m0 + row) * Rr + r] = s;
        }
        return;
    }

    // normal / x_b store
    float* Cw;
    if constexpr (SK == 1) {
        Cw = C;
    } else {
        Cw = C + (size_t)z * Bsz * N_;
    }
    int nbase = n0;
    int nstride = N_;
    if constexpr (FUSE_T) { nbase = n0 - XBN; nstride = XBN; }
    #pragma unroll
    for (int mt = 0; mt < 4; mt++) {
        int row0 = m0 + warp_m * 64 + mt * 16 + (lane >> 2);
        #pragma unroll
        for (int nt = 0; nt < NT; nt++) {
            int col = nbase + warp_n * WN + nt * 8 + (lane & 3) * 2;
            float bx = 0.f, by = 0.f;
            if constexpr (HAS_BIAS) { bx = biasv[nt].x; by = biasv[nt].y; }
            float2 v0 = make_float2(acc[mt][nt][0] + bx, acc[mt][nt][1] + by);
            float2 v1 = make_float2(acc[mt][nt][2] + bx, acc[mt][nt][3] + by);
            *reinterpret_cast<float2*>(&Cw[(size_t)row0 * nstride + col]) = v0;
            *reinterpret_cast<float2*>(&Cw[(size_t)(row0 + 8) * nstride + col]) = v1;
        }
    }
}

// ---------------------------------------------------------------------------
// reduce1: h = GELU(sum_z p1[z] + b1) -> bf16 hi/lo. 512 blocks x 2 elems.
// ---------------------------------------------------------------------------
__global__ void __launch_bounds__(256) reduce1_kernel(const float* __restrict__ b1)
{
    int e = (blockIdx.x * 256 + threadIdx.x) * 2;
    float2 p0 = *reinterpret_cast<const float2*>(&g_p1[e]);
    float2 p1v = *reinterpret_cast<const float2*>(&g_p1[1 * (Bsz * Dd) + e]);
    float2 p2 = *reinterpret_cast<const float2*>(&g_p1[2 * (Bsz * Dd) + e]);
    float2 p3 = *reinterpret_cast<const float2*>(&g_p1[3 * (Bsz * Dd) + e]);
    float2 bb = *reinterpret_cast<const float2*>(&b1[e & (Dd - 1)]);
    float u0 = p0.x + p1v.x + p2.x + p3.x + bb.x;
    float u1 = p0.y + p1v.y + p2.y + p3.y + bb.y;
    float g0 = 0.5f * u0 * (1.f + erff(u0 * 0.70710678118654752f));
    float g1 = 0.5f * u1 * (1.f + erff(u1 * 0.70710678118654752f));
    __nv_bfloat16 h0 = __float2bfloat16(g0), h1 = __float2bfloat16(g1);
    *reinterpret_cast<__nv_bfloat162*>(&g_Ahi[e]) = __halves2bfloat162(h0, h1);
    *reinterpret_cast<__nv_bfloat162*>(&g_Alo[e]) = __halves2bfloat162(
        __float2bfloat16(g0 - __bfloat162float(h0)),
        __float2bfloat16(g1 - __bfloat162float(h1)));
}

// ---------------------------------------------------------------------------
// reduce3: out = x + sum_z p3[z] + rank-8 epilogue; one block per b.
// ---------------------------------------------------------------------------
__global__ void __launch_bounds__(256) reduce3_kernel(
    const float* __restrict__ x, float* __restrict__ out)
{
    int b = blockIdx.x;
    __shared__ float t_s[Rr];
    {
        int p = threadIdx.x & 31, r = threadIdx.x >> 5;
        float v = g_tp[((size_t)p * Bsz + b) * Rr + r];
        #pragma unroll
        for (int o = 16; o; o >>= 1)
            v += __shfl_down_sync(0xFFFFFFFFu, v, o);
        if (p == 0) t_s[r] = v;
    }
    __syncthreads();

    int o = threadIdx.x * 4;
    size_t e = (size_t)b * Dd + o;
    float4 s = *reinterpret_cast<const float4*>(&x[e]);
    float4 q0 = *reinterpret_cast<const float4*>(&g_p3[0 * (Bsz * Dd) + e]);
    float4 q1 = *reinterpret_cast<const float4*>(&g_p3[1 * (Bsz * Dd) + e]);
    float4 q2 = *reinterpret_cast<const float4*>(&g_p3[2 * (Bsz * Dd) + e]);
    float4 q3 = *reinterpret_cast<const float4*>(&g_p3[3 * (Bsz * Dd) + e]);
    const float* wb = &g_w[(size_t)b * XBN + (size_t)o * Rr];
    float4 w[8];
    #pragma unroll
    for (int i = 0; i < 8; i++)
        w[i] = *reinterpret_cast<const float4*>(wb + i * 4);

    float t0 = t_s[0], t1 = t_s[1], t2 = t_s[2], t3 = t_s[3];
    float t4 = t_s[4], t5 = t_s[5], t6 = t_s[6], t7 = t_s[7];
    float lr[4];
    #pragma unroll
    for (int i = 0; i < 4; i++) {
        float4 wa = w[i * 2], wbv = w[i * 2 + 1];
        lr[i] = t0*wa.x + t1*wa.y + t2*wa.z + t3*wa.w
              + t4*wbv.x + t5*wbv.y + t6*wbv.z + t7*wbv.w;
    }
    float4 r;
    r.x = s.x + q0.x + q1.x + q2.x + q3.x + lr[0];
    r.y = s.y + q0.y + q1.y + q2.y + q3.y + lr[1];
    r.z = s.z + q0.z + q1.z + q2.z + q3.z + lr[2];
    r.w = s.w + q0.w + q1.w + q2.w + q3.w + lr[3];
    *reinterpret_cast<float4*>(&out[e]) = r;
}

// ---------------------------------------------------------------------------
extern "C" void kernel_launch(void* const* d_in, const int* in_sizes, int n_in,
                              void* d_out, int out_size)
{
    const float* x    = (const float*)d_in[0];
    const float* ada  = (const float*)d_in[1];
    const float* base = (const float*)d_in[2];
    const float* gam  = (const float*)d_in[3];
    const float* bet  = (const float*)d_in[4];
    const float* W1   = (const float*)d_in[5];
    const float* b1   = (const float*)d_in[6];
    const float* W2   = (const float*)d_in[7];
    const float* b2   = (const float*)d_in[8];
    float* out = (float*)d_out;

    constexpr int SMEM64  = 3 * (20480 + 128 * 64)  + 2 * (2 * 32 * 72 * 2);   // 104448
    constexpr int SMEM256 = 3 * (20480 + 128 * 256) + 2 * (2 * 32 * 264 * 2);  // 227328

    float *w_p, *p1_p, *p3_p;
    __nv_bfloat16 *chi_p, *clo_p, *ahi_p, *alo_p, *xhi_p;
    cudaGetSymbolAddress((void**)&w_p,  g_w);
    cudaGetSymbolAddress((void**)&p1_p, g_p1);
    cudaGetSymbolAddress((void**)&p3_p, g_p3);
    cudaGetSymbolAddress((void**)&chi_p, g_Chi);
    cudaGetSymbolAddress((void**)&clo_p, g_Clo);
    cudaGetSymbolAddress((void**)&ahi_p, g_Ahi);
    cudaGetSymbolAddress((void**)&alo_p, g_Alo);
    cudaGetSymbolAddress((void**)&xhi_p, g_Xhi);

    // k13: DUAL; problem 0 = gemm1 (3-pass), problem 1 = gemm3 (2-pass, no A-lo)
    auto k13 = gemm_mma_kernel<64, 4, false, 1024, 2, 4, true, 2, false, true>;
    // gemm2: 3-pass, fused t epilogue
    auto k2  = gemm_mma_kernel<256, 1, true, 16384, 2, 8, false, 1, true, false>;

    cudaFuncSetAttribute((const void*)k13,
                         cudaFuncAttributeMaxDynamicSharedMemorySize, SMEM64);
    cudaFuncSetAttribute((const void*)k2,
                         cudaFuncAttributeMaxDynamicSharedMemorySize, SMEM256);

    // prepass: LN (256 blocks) + x hi-split (512 blocks)
    prepass_kernel<<<768, 256>>>(ada, gam, bet, x);

    // GEMM1 + GEMM3 fused: z<4 -> cond@W1 partials (3-pass),
    //                      z>=4 -> x@base partials (2-pass)
    k13<<<dim3(16, 2, 8), 256, SMEM64>>>(
        chi_p, clo_p, W1, p1_p,
        xhi_p, nullptr, base, p3_p, nullptr, nullptr);

    // reduce1: + b1, GELU, split -> g_Ahi/g_Alo
    reduce1_kernel<<<(Bsz * Kd) / 512, 256>>>(b1);

    // GEMM2: single wave (128 CTAs, 512 thr); x_a half -> t partials, x_b -> g_w
    k2<<<dim3(W2N / 256, Bsz / BM, 1), 512, SMEM256>>>(
        ahi_p, alo_p, W2, w_p,
        nullptr, nullptr, nullptr, nullptr, b2, x);

    // final epilogue
    reduce3_kernel<<<Bsz, 256>>>(x, out);
}

// round 15
// speedup vs baseline: 1.3806x; 1.0436x over previous
#include <cuda_runtime.h>
#include <cuda_bf16.h>
#include <math.h>
#include <cstdint>

// ---------------------------------------------------------------------------
// AdaLoRAWithBase restructured:
//   out = x + x@base + sum_r t[b,r] * x_b[b,:,r],  t[b,r] = sum_c x[b,c]*x_a[b,c,r]
//   [x_a|x_b] = GELU(LN(ada)@W1+b1) @ W2 + b2
// R15: R14 + reduce1 fused into gemm2's PROLOGUE with a grid-wide spin barrier
// (safe: gemm2 = 128 CTAs at 1 CTA/SM on 148 SMs -> all co-resident).
// ---------------------------------------------------------------------------

namespace {
constexpr int Bsz = 256;
constexpr int Dd  = 1024;
constexpr int Aa  = 1024;
constexpr int Rr  = 8;
constexpr int W2N = Dd * Rr * 2;     // 16384
constexpr int XBN = Dd * Rr;         // 8192 (x_b width)
constexpr int Kd  = 1024;

constexpr int BM = 128, BK = 32;
constexpr int PSTG = 3;
constexpr int A_ROWB = 80;           // bytes per A smem row (40 bf16)
}

// Scratch (device globals)
__device__ __align__(16) float g_w[(size_t)Bsz * XBN];   // 8 MB (x_b only)
__device__ __align__(16) float g_tp[32 * Bsz * Rr];      // per-CTA t partials
__device__ __align__(16) float g_p1[4 * Bsz * Dd];
__device__ __align__(16) float g_p3[4 * Bsz * Dd];
__device__ __align__(16) __nv_bfloat16 g_Chi[Bsz * Kd];
__device__ __align__(16) __nv_bfloat16 g_Clo[Bsz * Kd];
__device__ __align__(16) __nv_bfloat16 g_Ahi[Bsz * Kd];
__device__ __align__(16) __nv_bfloat16 g_Alo[Bsz * Kd];
__device__ __align__(16) __nv_bfloat16 g_Xhi[Bsz * Kd];
__device__ int g_bar1;               // gemm2 prologue barrier counter

// ---------------------------------------------------------------------------
// PTX helpers (baseline sm_80+)
// ---------------------------------------------------------------------------
__device__ __forceinline__ uint32_t smem_u32(const void* p) {
    uint32_t a;
    asm("{ .reg .u64 t; cvta.to.shared.u64 t, %1; cvt.u32.u64 %0, t; }" : "=r"(a) : "l"(p));
    return a;
}
__device__ __forceinline__ void cp_async16(uint32_t saddr, const void* gaddr) {
    asm volatile("cp.async.cg.shared.global [%0], [%1], 16;" :: "r"(saddr), "l"(gaddr) : "memory");
}
__device__ __forceinline__ void cp_commit() {
    asm volatile("cp.async.commit_group;" ::: "memory");
}
template <int N>
__device__ __forceinline__ void cp_wait() {
    asm volatile("cp.async.wait_group %0;" :: "n"(N) : "memory");
}
__device__ __forceinline__ void ldsm_x4(uint32_t& r0, uint32_t& r1, uint32_t& r2, uint32_t& r3,
                                        uint32_t addr) {
    asm volatile("ldmatrix.sync.aligned.m8n8.x4.shared.b16 {%0,%1,%2,%3}, [%4];"
                 : "=r"(r0), "=r"(r1), "=r"(r2), "=r"(r3) : "r"(addr));
}
__device__ __forceinline__ void ldsm_x4_trans(uint32_t& r0, uint32_t& r1, uint32_t& r2,
                                              uint32_t& r3, uint32_t addr) {
    asm volatile("ldmatrix.sync.aligned.m8n8.x4.trans.shared.b16 {%0,%1,%2,%3}, [%4];"
                 : "=r"(r0), "=r"(r1), "=r"(r2), "=r"(r3) : "r"(addr));
}
__device__ __forceinline__ void mma16816(float* c, uint32_t a0, uint32_t a1, uint32_t a2,
                                         uint32_t a3, uint32_t b0, uint32_t b1) {
    asm volatile(
        "mma.sync.aligned.m16n8k16.row.col.f32.bf16.bf16.f32 "
        "{%0,%1,%2,%3},{%4,%5,%6,%7},{%8,%9},{%0,%1,%2,%3};"
        : "+f"(c[0]), "+f"(c[1]), "+f"(c[2]), "+f"(c[3])
        : "r"(a0), "r"(a1), "r"(a2), "r"(a3), "r"(b0), "r"(b1));
}
// pack two fp32 -> bf16x2 (RN); a -> low half, b -> high half
__device__ __forceinline__ uint32_t bf16x2_rn(float a, float b) {
    uint32_t r;
    asm("cvt.rn.bf16x2.f32 %0, %2, %1;" : "=r"(r) : "f"(a), "f"(b));
    return r;
}

// ---------------------------------------------------------------------------
// Merged pre-pass: blocks [0,256) do LayerNorm rows; blocks [256,768) split x
// (hi only). Block 0 resets the gemm2 barrier counter.
// ---------------------------------------------------------------------------
__global__ void __launch_bounds__(256) prepass_kernel(
    const float* __restrict__ ada, const float* __restrict__ gamma,
    const float* __restrict__ beta, const float* __restrict__ x)
{
    if (blockIdx.x == 0 && threadIdx.x == 0) g_bar1 = 0;
    if (blockIdx.x < 256) {
        int b = blockIdx.x;
        const float* row = ada + (size_t)b * Aa;
        float s = 0.f, s2 = 0.f;
        for (int i = threadIdx.x; i < Aa; i += blockDim.x) {
            float v = row[i]; s += v; s2 += v * v;
        }
        #pragma unroll
        for (int o = 16; o; o >>= 1) {
            s  += __shfl_down_sync(0xFFFFFFFFu, s,  o);
            s2 += __shfl_down_sync(0xFFFFFFFFu, s2, o);
        }
        __shared__ float red0[8], red1[8], mv[2];
        int wid = threadIdx.x >> 5, lid = threadIdx.x & 31;
        if (lid == 0) { red0[wid] = s; red1[wid] = s2; }
        __syncthreads();
        if (threadIdx.x == 0) {
            float ts = 0.f, ts2 = 0.f;
            #pragma unroll
            for (int i = 0; i < 8; i++) { ts += red0[i]; ts2 += red1[i]; }
            float mu = ts * (1.f / Aa);
            float var = ts2 * (1.f / Aa) - mu * mu;
            mv[0] = mu; mv[1] = rsqrtf(var + 1e-5f);
        }
        __syncthreads();
        float mu = mv[0], rs = mv[1];
        for (int i = threadIdx.x; i < Aa; i += blockDim.x) {
            float v = (row[i] - mu) * rs * gamma[i] + beta[i];
            __nv_bfloat16 hi = __float2bfloat16(v);
            g_Chi[(size_t)b * Aa + i] = hi;
            g_Clo[(size_t)b * Aa + i] = __float2bfloat16(v - __bfloat162float(hi));
        }
    } else {
        int i = ((blockIdx.x - 256) * 256 + threadIdx.x) * 2;
        float v0 = x[i], v1 = x[i + 1];
        *reinterpret_cast<__nv_bfloat162*>(&g_Xhi[i]) =
            __halves2bfloat162(__float2bfloat16(v0), __float2bfloat16(v1));
    }
}

// ---------------------------------------------------------------------------
// Unified bf16 hi/lo MMA GEMM, fused fp32 B conversion, PSTG=3.
// 3-pass by default; per-problem 2-pass (drop A-lo).
// FUSE_T: x_a-half CTAs compute t partials.
// FUSE_R1: prologue performs reduce1 slice + grid-wide spin barrier
//          (requires grid <= #SMs at this occupancy; gemm2: 128 CTAs, 1/SM).
// ---------------------------------------------------------------------------
template <int BN_, int N_, int NTHR>
__device__ __forceinline__ void load_grp(
    uint32_t sstage, const __nv_bfloat16* __restrict__ ahi,
    const __nv_bfloat16* __restrict__ alo, const float* __restrict__ Braw,
    int m0, int n0, int k0, int tid, bool load_alo)
{
    constexpr int RCHR = BN_ / 4;
    constexpr int TOT = 1024 + 8 * BN_;
    #pragma unroll
    for (int it = 0; it < TOT / NTHR; it++) {
        int idx = tid + it * NTHR;
        if (idx < 512) {
            int row = idx >> 2, ch = idx & 3;
            cp_async16(sstage + row * A_ROWB + ch * 16,
                       &ahi[(size_t)(m0 + row) * Kd + k0 + ch * 8]);
        } else if (idx < 1024) {
            if (load_alo) {
                int l = idx - 512, row = l >> 2, ch = l & 3;
                cp_async16(sstage + 10240 + row * A_ROWB + ch * 16,
                           &alo[(size_t)(m0 + row) * Kd + k0 + ch * 8]);
            }
        } else {
            int l = idx - 1024;
            int row = l / RCHR, ch = l % RCHR;
            cp_async16(sstage + 20480 + row * (BN_ * 4) + ch * 16,
                       &Braw[(size_t)(k0 + row) * N_ + n0 + ch * 4]);
        }
    }
    cp_commit();
}

template <int BN_, int NTHR>
__device__ __forceinline__ void conv_b(char* smem, uint32_t raw_off, uint32_t bb_off,
                                       uint32_t bb_half, int tid)
{
    constexpr int B_RL = BN_ + 8;
    constexpr int RC = 8 * BN_;
    #pragma unroll
    for (int i = 0; i < RC / NTHR; i++) {
        int c = tid + i * NTHR;
        float4 v = *reinterpret_cast<const float4*>(smem + raw_off + c * 16);
        int row = c / (BN_ / 4);
        int col = (c % (BN_ / 4)) * 4;
        uint32_t hi01 = bf16x2_rn(v.x, v.y);
        uint32_t hi23 = bf16x2_rn(v.z, v.w);
        float h0 = __uint_as_float(hi01 << 16);
        float h1 = __uint_as_float(hi01 & 0xFFFF0000u);
        float h2 = __uint_as_float(hi23 << 16);
        float h3 = __uint_as_float(hi23 & 0xFFFF0000u);
        uint32_t lo01 = bf16x2_rn(v.x - h0, v.y - h1);
        uint32_t lo23 = bf16x2_rn(v.z - h2, v.w - h3);
        uint32_t eoff = (uint32_t)(row * B_RL + col) * 2;
        *reinterpret_cast<uint2*>(smem + bb_off + eoff)           = make_uint2(hi01, hi23);
        *reinterpret_cast<uint2*>(smem + bb_off + bb_half + eoff) = make_uint2(lo01, lo23);
    }
}

template <int BN_, int SK, bool HAS_BIAS, int N_, int NWM, int NWN, bool DUAL,
          int MINB, bool FUSE_T, bool TWOPASS1, bool FUSE_R1>
__global__ void __launch_bounds__(NWM * NWN * 32, MINB) gemm_mma_kernel(
    const __nv_bfloat16* __restrict__ ahi0, const __nv_bfloat16* __restrict__ alo0,
    const float* __restrict__ Braw0, float* __restrict__ C0,
    const __nv_bfloat16* __restrict__ ahi1, const __nv_bfloat16* __restrict__ alo1,
    const float* __restrict__ Braw1, float* __restrict__ C1,
    const float* __restrict__ bias, const float* __restrict__ xsrc,
    const float* __restrict__ b1v)
{
    constexpr int NTHR = NWM * NWN * 32;
    constexpr int WN   = BN_ / NWN;
    constexpr int NT   = WN / 8;
    constexpr int B_RL = BN_ + 8;
    constexpr int STG  = 20480 + 128 * BN_;
    constexpr int OFF_BBc = PSTG * STG;
    constexpr int BB_HALFc = 32 * B_RL * 2;
    constexpr int BB_SZc = 2 * BB_HALFc;
    constexpr int KITERS = Kd / SK / BK;

    extern __shared__ char smem[];
    uint32_t sb = smem_u32(smem);
    const int tid = threadIdx.x, lane = tid & 31, wid = tid >> 5;
    const int warp_m = wid / NWN, warp_n = wid % NWN;
    const int m0 = blockIdx.y * BM, n0 = blockIdx.x * BN_;

    // ---- FUSE_R1: reduce1 slice + grid-wide spin barrier (all-resident) ----
    if constexpr (FUSE_R1) {
        int cid = blockIdx.y * gridDim.x + blockIdx.x;       // 0..127
        int e = cid * (NTHR * 4) + tid * 4;                  // covers Bsz*Kd
        float4 s = *reinterpret_cast<const float4*>(&g_p1[e]);
        #pragma unroll
        for (int zz = 1; zz < 4; zz++) {
            float4 p = *reinterpret_cast<const float4*>(&g_p1[zz * (Bsz * Dd) + e]);
            s.x += p.x; s.y += p.y; s.z += p.z; s.w += p.w;
        }
        float4 bb = *reinterpret_cast<const float4*>(&b1v[e & (Dd - 1)]);
        float u[4] = {s.x + bb.x, s.y + bb.y, s.z + bb.z, s.w + bb.w};
        __nv_bfloat16 hi[4], lo[4];
        #pragma unroll
        for (int q = 0; q < 4; q++) {
            float g = 0.5f * u[q] * (1.f + erff(u[q] * 0.70710678118654752f));
            hi[q] = __float2bfloat16(g);
            lo[q] = __float2bfloat16(g - __bfloat162float(hi[q]));
        }
        *reinterpret_cast<__nv_bfloat162*>(&g_Ahi[e])     = __halves2bfloat162(hi[0], hi[1]);
        *reinterpret_cast<__nv_bfloat162*>(&g_Ahi[e + 2]) = __halves2bfloat162(hi[2], hi[3]);
        *reinterpret_cast<__nv_bfloat162*>(&g_Alo[e])     = __halves2bfloat162(lo[0], lo[1]);
        *reinterpret_cast<__nv_bfloat162*>(&g_Alo[e + 2]) = __halves2bfloat162(lo[2], lo[3]);
        __threadfence();
        __syncthreads();
        if (tid == 0) {
            atomicAdd(&g_bar1, 1);
            while (*reinterpret_cast<volatile int*>(&g_bar1) <
                   (int)(gridDim.x * gridDim.y)) { }
        }
        __syncthreads();
    }

    int z = blockIdx.z;
    const __nv_bfloat16* ahi = ahi0;
    const __nv_bfloat16* alo = alo0;
    const float* Braw = Braw0;
    float* C = C0;
    const bool threep = !(TWOPASS1 && DUAL && blockIdx.z >= SK);
    if (DUAL && z >= SK) {
        z -= SK; ahi = ahi1; alo = alo1; Braw = Braw1; C = C1;
    }
    const int kb = z * (Kd / SK);

    float acc[4][NT][4];
    #pragma unroll
    for (int i = 0; i < 4; i++)
        #pragma unroll
        for (int j = 0; j < NT; j++)
            #pragma unroll
            for (int r = 0; r < 4; r++) acc[i][j][r] = 0.f;

    float2 biasv[NT];
    if constexpr (HAS_BIAS) {
        #pragma unroll
        for (int nt = 0; nt < NT; nt++)
            biasv[nt] = *reinterpret_cast<const float2*>(
                &bias[n0 + warp_n * WN + nt * 8 + (lane & 3) * 2]);
    }

    load_grp<BN_, N_, NTHR>(sb, ahi, alo, Braw, m0, n0, kb, tid, threep);
    load_grp<BN_, N_, NTHR>(sb + STG, ahi, alo, Braw, m0, n0, kb + BK, tid, threep);

    cp_wait<1>();
    conv_b<BN_, NTHR>(smem, 20480, OFF_BBc, BB_HALFc, tid);

    const int a_row_in_tile = lane & 15;
    const int a_colblk = (lane >> 4) << 3;
    const int b_krow = (lane & 7) + ((lane >> 3) & 1) * 8;
    const int b_cofs = warp_n * WN + ((lane >> 4) & 1) * 8;

    for (int kt = 0; kt < KITERS; kt++) {
        cp_wait<0>();
        __syncthreads();

        if (kt + 2 < KITERS)
            load_grp<BN_, N_, NTHR>(sb + ((kt + 2) % PSTG) * STG, ahi, alo, Braw,
                                    m0, n0, kb + (kt + 2) * BK, tid, threep);
        if (kt + 1 < KITERS)
            conv_b<BN_, NTHR>(smem, ((kt + 1) % PSTG) * STG + 20480,
                              OFF_BBc + ((kt + 1) & 1) * BB_SZc, BB_HALFc, tid);

        uint32_t abase = sb + (kt % PSTG) * STG;
        uint32_t bbase = sb + OFF_BBc + (kt & 1) * BB_SZc;

        #pragma unroll
        for (int ks = 0; ks < 2; ks++) {
            uint32_t af[4][4], bf[NT][2], bl2[NT][2];
            #pragma unroll
            for (int mt = 0; mt < 4; mt++) {
                int row = warp_m * 64 + mt * 16 + a_row_in_tile;
                uint32_t off = (uint32_t)(row * 40 + ks * 16 + a_colblk) * 2;
                ldsm_x4(af[mt][0], af[mt][1], af[mt][2], af[mt][3], abase + off);
            }
            #pragma unroll
            for (int ntp = 0; ntp < NT / 2; ntp++) {
                uint32_t off = (uint32_t)((ks * 16 + b_krow) * B_RL + b_cofs + ntp * 16) * 2;
                ldsm_x4_trans(bf[2*ntp][0], bf[2*ntp][1], bf[2*ntp+1][0], bf[2*ntp+1][1],
                              bbase + off);
            }
            #pragma unroll
            for (int mt = 0; mt < 4; mt++)
                #pragma unroll
                for (int nt = 0; nt < NT; nt++)
                    mma16816(acc[mt][nt], af[mt][0], af[mt][1], af[mt][2], af[mt][3],
                             bf[nt][0], bf[nt][1]);
            #pragma unroll
            for (int ntp = 0; ntp < NT / 2; ntp++) {
                uint32_t off = (uint32_t)((ks * 16 + b_krow) * B_RL + b_cofs + ntp * 16) * 2;
                ldsm_x4_trans(bl2[2*ntp][0], bl2[2*ntp][1], bl2[2*ntp+1][0], bl2[2*ntp+1][1],
                              bbase + BB_HALFc + off);
            }
            #pragma unroll
            for (int mt = 0; mt < 4; mt++)
                #pragma unroll
                for (int nt = 0; nt < NT; nt++)
                    mma16816(acc[mt][nt], af[mt][0], af[mt][1], af[mt][2], af[mt][3],
                             bl2[nt][0], bl2[nt][1]);
            if (threep) {
                #pragma unroll
                for (int mt = 0; mt < 4; mt++) {
                    int row = warp_m * 64 + mt * 16 + a_row_in_tile;
                    uint32_t off = (uint32_t)(row * 40 + ks * 16 + a_colblk) * 2;
                    ldsm_x4(af[mt][0], af[mt][1], af[mt][2], af[mt][3],
                            abase + 10240 + off);
                }
                #pragma unroll
                for (int mt = 0; mt < 4; mt++)
                    #pragma unroll
                    for (int nt = 0; nt < NT; nt++)
                        mma16816(acc[mt][nt], af[mt][0], af[mt][1], af[mt][2], af[mt][3],
                                 bf[nt][0], bf[nt][1]);
            }
        }
    }

    if (FUSE_T && blockIdx.x < (XBN / BN_)) {
        // x_a half: t partials. Each nt fragment = one d, r=0..7.
        float* tpart = (float*)smem;                          // [NWN][128][8]
        float* x_s = (float*)(smem + NWN * 128 * 8 * 4);      // [128][32]
        __syncthreads();
        {
            int d0 = n0 / 8;
            int row = tid >> 2, ch = tid & 3;
            float4 v = *reinterpret_cast<const float4*>(
                &xsrc[(size_t)(m0 + row) * Dd + d0 + ch * 8]);
            float4 v2 = *reinterpret_cast<const float4*>(
                &xsrc[(size_t)(m0 + row) * Dd + d0 + ch * 8 + 4]);
            *reinterpret_cast<float4*>(&x_s[row * 32 + ch * 8]) = v;
            *reinterpret_cast<float4*>(&x_s[row * 32 + ch * 8 + 4]) = v2;
        }
        __syncthreads();

        int r0 = (lane & 3) * 2;
        #pragma unroll
        for (int mt = 0; mt < 4; mt++) {
            int row_a = warp_m * 64 + mt * 16 + (lane >> 2);
            int row_b = row_a + 8;
            float t00 = 0.f, t01 = 0.f, t10 = 0.f, t11 = 0.f;
            #pragma unroll
            for (int nt = 0; nt < NT; nt++) {
                int dl = warp_n * NT + nt;
                float xa = x_s[row_a * 32 + dl];
                float xb = x_s[row_b * 32 + dl];
                float bx = 0.f, by = 0.f;
                if constexpr (HAS_BIAS) { bx = biasv[nt].x; by = biasv[nt].y; }
                t00 += xa * (acc[mt][nt][0] + bx);
                t01 += xa * (acc[mt][nt][1] + by);
                t10 += xb * (acc[mt][nt][2] + bx);
                t11 += xb * (acc[mt][nt][3] + by);
            }
            tpart[(warp_n * 128 + row_a) * 8 + r0]     = t00;
            tpart[(warp_n * 128 + row_a) * 8 + r0 + 1] = t01;
            tpart[(warp_n * 128 + row_b) * 8 + r0]     = t10;
            tpart[(warp_n * 128 + row_b) * 8 + r0 + 1] = t11;
        }
        __syncthreads();
        #pragma unroll
        for (int i = 0; i < 2; i++) {
            int pr = tid + i * NTHR;
            int row = pr >> 3, r = pr & 7;
            float s = 0.f;
            #pragma unroll
            for (int w = 0; w < NWN; w++)
                s += tpart[(w * 128 + row) * 8 + r];
            g_tp[((size_t)blockIdx.x * Bsz + m0 + row) * Rr + r] = s;
        }
        return;
    }

    // normal / x_b store
    float* Cw;
    if constexpr (SK == 1) {
        Cw = C;
    } else {
        Cw = C + (size_t)z * Bsz * N_;
    }
    int nbase = n0;
    int nstride = N_;
    if constexpr (FUSE_T) { nbase = n0 - XBN; nstride = XBN; }
    #pragma unroll
    for (int mt = 0; mt < 4; mt++) {
        int row0 = m0 + warp_m * 64 + mt * 16 + (lane >> 2);
        #pragma unroll
        for (int nt = 0; nt < NT; nt++) {
            int col = nbase + warp_n * WN + nt * 8 + (lane & 3) * 2;
            float bx = 0.f, by = 0.f;
            if constexpr (HAS_BIAS) { bx = biasv[nt].x; by = biasv[nt].y; }
            float2 v0 = make_float2(acc[mt][nt][0] + bx, acc[mt][nt][1] + by);
            float2 v1 = make_float2(acc[mt][nt][2] + bx, acc[mt][nt][3] + by);
            *reinterpret_cast<float2*>(&Cw[(size_t)row0 * nstride + col]) = v0;
            *reinterpret_cast<float2*>(&Cw[(size_t)(row0 + 8) * nstride + col]) = v1;
        }
    }
}

// ---------------------------------------------------------------------------
// reduce3: out = x + sum_z p3[z] + rank-8 epilogue; one block per b.
// ---------------------------------------------------------------------------
__global__ void __launch_bounds__(256) reduce3_kernel(
    const float* __restrict__ x, float* __restrict__ out)
{
    int b = blockIdx.x;
    __shared__ float t_s[Rr];
    {
        int p = threadIdx.x & 31, r = threadIdx.x >> 5;
        float v = g_tp[((size_t)p * Bsz + b) * Rr + r];
        #pragma unroll
        for (int o = 16; o; o >>= 1)
            v += __shfl_down_sync(0xFFFFFFFFu, v, o);
        if (p == 0) t_s[r] = v;
    }
    __syncthreads();

    int o = threadIdx.x * 4;
    size_t e = (size_t)b * Dd + o;
    float4 s = *reinterpret_cast<const float4*>(&x[e]);
    float4 q0 = *reinterpret_cast<const float4*>(&g_p3[0 * (Bsz * Dd) + e]);
    float4 q1 = *reinterpret_cast<const float4*>(&g_p3[1 * (Bsz * Dd) + e]);
    float4 q2 = *reinterpret_cast<const float4*>(&g_p3[2 * (Bsz * Dd) + e]);
    float4 q3 = *reinterpret_cast<const float4*>(&g_p3[3 * (Bsz * Dd) + e]);
    const float* wb = &g_w[(size_t)b * XBN + (size_t)o * Rr];
    float4 w[8];
    #pragma unroll
    for (int i = 0; i < 8; i++)
        w[i] = *reinterpret_cast<const float4*>(wb + i * 4);

    float t0 = t_s[0], t1 = t_s[1], t2 = t_s[2], t3 = t_s[3];
    float t4 = t_s[4], t5 = t_s[5], t6 = t_s[6], t7 = t_s[7];
    float lr[4];
    #pragma unroll
    for (int i = 0; i < 4; i++) {
        float4 wa = w[i * 2], wbv = w[i * 2 + 1];
        lr[i] = t0*wa.x + t1*wa.y + t2*wa.z + t3*wa.w
              + t4*wbv.x + t5*wbv.y + t6*wbv.z + t7*wbv.w;
    }
    float4 r;
    r.x = s.x + q0.x + q1.x + q2.x + q3.x + lr[0];
    r.y = s.y + q0.y + q1.y + q2.y + q3.y + lr[1];
    r.z = s.z + q0.z + q1.z + q2.z + q3.z + lr[2];
    r.w = s.w + q0.w + q1.w + q2.w + q3.w + lr[3];
    *reinterpret_cast<float4*>(&out[e]) = r;
}

// ---------------------------------------------------------------------------
extern "C" void kernel_launch(void* const* d_in, const int* in_sizes, int n_in,
                              void* d_out, int out_size)
{
    const float* x    = (const float*)d_in[0];
    const float* ada  = (const float*)d_in[1];
    const float* base = (const float*)d_in[2];
    const float* gam  = (const float*)d_in[3];
    const float* bet  = (const float*)d_in[4];
    const float* W1   = (const float*)d_in[5];
    const float* b1   = (const float*)d_in[6];
    const float* W2   = (const float*)d_in[7];
    const float* b2   = (const float*)d_in[8];
    float* out = (float*)d_out;

    constexpr int SMEM64  = 3 * (20480 + 128 * 64)  + 2 * (2 * 32 * 72 * 2);   // 104448
    constexpr int SMEM256 = 3 * (20480 + 128 * 256) + 2 * (2 * 32 * 264 * 2);  // 227328

    float *w_p, *p1_p, *p3_p;
    __nv_bfloat16 *chi_p, *clo_p, *ahi_p, *alo_p, *xhi_p;
    cudaGetSymbolAddress((void**)&w_p,  g_w);
    cudaGetSymbolAddress((void**)&p1_p, g_p1);
    cudaGetSymbolAddress((void**)&p3_p, g_p3);
    cudaGetSymbolAddress((void**)&chi_p, g_Chi);
    cudaGetSymbolAddress((void**)&clo_p, g_Clo);
    cudaGetSymbolAddress((void**)&ahi_p, g_Ahi);
    cudaGetSymbolAddress((void**)&alo_p, g_Alo);
    cudaGetSymbolAddress((void**)&xhi_p, g_Xhi);

    // k13: DUAL; problem 0 = gemm1 (3-pass), problem 1 = gemm3 (2-pass)
    auto k13 = gemm_mma_kernel<64, 4, false, 1024, 2, 4, true, 2, false, true, false>;
    // gemm2: 3-pass, fused t epilogue + fused reduce1 prologue
    auto k2  = gemm_mma_kernel<256, 1, true, 16384, 2, 8, false, 1, true, false, true>;

    cudaFuncSetAttribute((const void*)k13,
                         cudaFuncAttributeMaxDynamicSharedMemorySize, SMEM64);
    cudaFuncSetAttribute((const void*)k2,
                         cudaFuncAttributeMaxDynamicSharedMemorySize, SMEM256);

    // prepass: barrier reset + LN (256 blocks) + x hi-split (512 blocks)
    prepass_kernel<<<768, 256>>>(ada, gam, bet, x);

    // GEMM1 + GEMM3 fused: z<4 -> cond@W1 partials (3-pass),
    //                      z>=4 -> x@base partials (2-pass)
    k13<<<dim3(16, 2, 8), 256, SMEM64>>>(
        chi_p, clo_p, W1, p1_p,
        xhi_p, nullptr, base, p3_p, nullptr, nullptr, nullptr);

    // GEMM2: reduce1 fused in prologue (grid-wide barrier, all CTAs resident);
    // x_a half -> t partials, x_b -> g_w
    k2<<<dim3(W2N / 256, Bsz / BM, 1), 512, SMEM256>>>(
        ahi_p, alo_p, W2, w_p,
        nullptr, nullptr, nullptr, nullptr, b2, x, b1);

    // final epilogue
    reduce3_kernel<<<Bsz, 256>>>(x, out);
}